// round 12
// baseline (speedup 1.0000x reference)
#include <cuda_runtime.h>
#include <cuda_bf16.h>
#include <cstdint>

#define BB 2
#define SS 2048
#define DM 1024
#define HH 16
#define DK 64

typedef unsigned long long ull;

#define ACT_N ((size_t)4096 * 1024)
#define W_N   ((size_t)1024 * 1024)

// Scratch (__device__ globals; allocation-free rule)
__device__ __align__(16) __nv_bfloat16 g_act_hi[3 * ACT_N];   // q,k,v inputs split
__device__ __align__(16) __nv_bfloat16 g_act_lo[3 * ACT_N];
__device__ __align__(16) __nv_bfloat16 g_w_hi[4 * W_N];       // wq,wk,wv,wo split
__device__ __align__(16) __nv_bfloat16 g_w_lo[4 * W_N];
__device__ __align__(16) __nv_bfloat16 g_q_hi[BB*HH*SS*DK];   // [BH][S][64] (x0.125*log2e)
__device__ __align__(16) __nv_bfloat16 g_q_lo[BB*HH*SS*DK];
__device__ __align__(16) __nv_bfloat16 g_k_hi[BB*HH*SS*DK];   // [BH][S][64]
__device__ __align__(16) __nv_bfloat16 g_k_lo[BB*HH*SS*DK];
__device__ __align__(16) __nv_bfloat16 g_vt_hi[BB*HH*SS*DK];  // [BH][64][S]  (V^T)
__device__ __align__(16) __nv_bfloat16 g_vt_lo[BB*HH*SS*DK];
__device__ __align__(16) __nv_bfloat16 g_attn_hi[ACT_N];      // flash out split
__device__ __align__(16) __nv_bfloat16 g_attn_lo[ACT_N];

// ---------------- helpers ----------------
__device__ __forceinline__ uint32_t smem_u32(const void* p) {
    uint32_t a;
    asm("{ .reg .u64 t; cvta.to.shared.u64 t, %1; cvt.u32.u64 %0, t; }"
        : "=r"(a) : "l"(p));
    return a;
}
__device__ __forceinline__ uint64_t gmem_u64(const void* p) {
    uint64_t a;
    asm("cvta.to.global.u64 %0, %1;" : "=l"(a) : "l"(p));
    return a;
}
__device__ __forceinline__ uint32_t elect_one() {
    uint32_t p;
    asm volatile("{ .reg .pred p; elect.sync _|p, 0xFFFFFFFF; selp.b32 %0,1,0,p; }"
                 : "=r"(p));
    return p;
}
__device__ __forceinline__ void mma16816(float* c, const uint32_t* a, const uint32_t* b) {
    asm volatile(
        "mma.sync.aligned.m16n8k16.row.col.f32.bf16.bf16.f32 "
        "{%0,%1,%2,%3}, {%4,%5,%6,%7}, {%8,%9}, {%0,%1,%2,%3};"
        : "+f"(c[0]), "+f"(c[1]), "+f"(c[2]), "+f"(c[3])
        : "r"(a[0]), "r"(a[1]), "r"(a[2]), "r"(a[3]), "r"(b[0]), "r"(b[1]));
}
__device__ __forceinline__ void ldmx4(uint32_t* r, uint32_t addr) {
    asm volatile("ldmatrix.sync.aligned.m8n8.x4.shared.b16 {%0,%1,%2,%3}, [%4];"
                 : "=r"(r[0]), "=r"(r[1]), "=r"(r[2]), "=r"(r[3]) : "r"(addr));
}
__device__ __forceinline__ void cp16(uint32_t saddr, uint64_t gaddr) {
    asm volatile("cp.async.cg.shared.global [%0], [%1], 16;"
                 :: "r"(saddr), "l"(gaddr) : "memory");
}
#define CP_COMMIT() asm volatile("cp.async.commit_group;" ::: "memory")
#define CP_WAIT(n)  asm volatile("cp.async.wait_group %0;" :: "n"(n) : "memory")

#define MBARRIER_INIT(a, n) \
    asm volatile("mbarrier.init.shared.b64 [%0], %1;" :: "r"(a), "r"(n) : "memory")
#define MBARRIER_ARRIVE(a) \
    asm volatile("mbarrier.arrive.shared.b64 _, [%0];" :: "r"(a) : "memory")
#define MBAR_WAIT(a, ph) do {                                                     \
    asm volatile("{\n\t.reg .pred P;\n\t"                                         \
        "W_%=:\n\t"                                                               \
        "mbarrier.try_wait.parity.acquire.cta.shared::cta.b64 P, [%0], %1, 0x989680;\n\t" \
        "@P bra.uni D_%=;\n\t"                                                    \
        "bra.uni W_%=;\n\t"                                                       \
        "D_%=:\n\t}"                                                              \
        :: "r"(a), "r"(ph) : "memory");                                           \
} while (0)

__device__ __forceinline__ uint32_t swz(uint32_t x) { return x ^ ((x >> 3) & 0x70); }

__device__ __forceinline__ float ex2f(float x) {
    float y; asm("ex2.approx.f32 %0, %1;" : "=f"(y) : "f"(x)); return y;
}

// pack two fp32 -> bf16x2 hi + bf16x2 residual lo
__device__ __forceinline__ void pack_hilo(float x0, float x1, uint32_t& hi, uint32_t& lo) {
    uint32_t h;
    asm("cvt.rn.bf16x2.f32 %0, %1, %2;" : "=r"(h) : "f"(x1), "f"(x0));
    const float h0 = __uint_as_float(h << 16);
    const float h1 = __uint_as_float(h & 0xffff0000u);
    uint32_t l;
    asm("cvt.rn.bf16x2.f32 %0, %1, %2;" : "=r"(l) : "f"(x1 - h1), "f"(x0 - h0));
    hi = h; lo = l;
}

// ---------------------------------------------------------------------------
// Split fp32 -> bf16 hi/lo.  z=0..2: q,k,v inputs ; z=3..6: wq,wk,wv,wo
// ---------------------------------------------------------------------------
__global__ void __launch_bounds__(256)
split_kernel(const float* __restrict__ q, const float* __restrict__ k,
             const float* __restrict__ v,
             const float* __restrict__ wq, const float* __restrict__ wk,
             const float* __restrict__ wv, const float* __restrict__ wo)
{
    const int z = blockIdx.z;
    const float* src;
    __nv_bfloat16 *dh, *dl;
    size_t cnt;
    if (z < 3) {
        src = (z == 0) ? q : (z == 1) ? k : v;
        dh = g_act_hi + (size_t)z * ACT_N;
        dl = g_act_lo + (size_t)z * ACT_N;
        cnt = ACT_N;
    } else {
        const int w = z - 3;
        src = (w == 0) ? wq : (w == 1) ? wk : (w == 2) ? wv : wo;
        dh = g_w_hi + (size_t)w * W_N;
        dl = g_w_lo + (size_t)w * W_N;
        cnt = W_N;
    }
    const size_t i4 = (size_t)blockIdx.x * 256 + threadIdx.x;
    if (i4 * 4 >= cnt) return;
    float4 x = ((const float4*)src)[i4];
    uint32_t h01, l01, h23, l23;
    pack_hilo(x.x, x.y, h01, l01);
    pack_hilo(x.z, x.w, h23, l23);
    *(uint2*)&dh[i4 * 4] = make_uint2(h01, h23);
    *(uint2*)&dl[i4 * 4] = make_uint2(l01, l23);
}

// ---------------------------------------------------------------------------
// HMMA split-bf16 GEMM, 3-stage cp.async pipeline (unchanged control).
// ---------------------------------------------------------------------------
#define STAGE_BYTES 65536
#define TC_SMEM (3 * STAGE_BYTES)

template <int MODE>
__device__ __forceinline__ void gemm_tc(int m0, int n0,
                                        const __nv_bfloat16* __restrict__ Ah,
                                        const __nv_bfloat16* __restrict__ Al,
                                        const __nv_bfloat16* __restrict__ Bh,
                                        const __nv_bfloat16* __restrict__ Bl,
                                        const float* __restrict__ bias,
                                        float* __restrict__ C,
                                        __nv_bfloat16* __restrict__ Dh,
                                        __nv_bfloat16* __restrict__ Dl,
                                        float oscale)
{
    extern __shared__ char sm[];
    const uint32_t smb = smem_u32(sm);
    const int tid  = threadIdx.x;
    const int wid  = tid >> 5;
    const int lane = tid & 31;

    const int warp_m = (wid >> 2) << 6;
    const int warp_n = (wid & 3) << 5;

    uint64_t gb[4];
    gb[0] = gmem_u64(Ah + (size_t)m0 * 1024);
    gb[1] = gmem_u64(Al + (size_t)m0 * 1024);
    gb[2] = gmem_u64(Bh + (size_t)n0 * 1024);
    gb[3] = gmem_u64(Bl + (size_t)n0 * 1024);

    const int lr = tid >> 3;
    const int lc = tid & 7;

    const int arow = warp_m + (lane & 15);
    const int a_chi = lane >> 4;
    const int ax = arow & 7;
    const uint32_t arow128 = (uint32_t)arow * 128;
    const int g = lane >> 3;
    const int brow = warp_n + ((g >> 1) << 3) + (lane & 7);
    const int b_chi = g & 1;
    const int bx = brow & 7;
    const uint32_t brow128 = (uint32_t)brow * 128;

    float acc[4][4][4];
#pragma unroll
    for (int mi = 0; mi < 4; mi++)
#pragma unroll
        for (int nj = 0; nj < 4; nj++)
#pragma unroll
            for (int r = 0; r < 4; r++) acc[mi][nj][r] = 0.f;

    auto issue_chunk = [&](int c) {
        const int k0 = c << 6;
        const uint32_t st = smb + (uint32_t)(c % 3) * STAGE_BYTES;
#pragma unroll
        for (int op = 0; op < 4; op++) {
#pragma unroll
            for (int rb = 0; rb < 4; rb++) {
                const int row = (rb << 5) + lr;
                const uint64_t ga = gb[op] + ((size_t)row * 1024 + k0 + (lc << 3)) * 2;
                const uint32_t sa = st + op * 16384 + swz((uint32_t)row * 128 + (lc << 4));
                cp16(sa, ga);
            }
        }
        CP_COMMIT();
    };

    issue_chunk(0);
    issue_chunk(1);

    for (int c = 0; c < 16; c++) {
        if (c < 15) { CP_WAIT(1); } else { CP_WAIT(0); }
        __syncthreads();
        if (c + 2 < 16) issue_chunk(c + 2);

        const uint32_t st = smb + (uint32_t)(c % 3) * STAGE_BYTES;

#pragma unroll
        for (int ks = 0; ks < 4; ks++) {
            uint32_t Ahf[4][4], Alf[4][4], Bhf[4][2], Blf[4][2];
            const uint32_t acol = (uint32_t)((((ks << 1) | a_chi) ^ ax) << 4);
            const uint32_t bcol = (uint32_t)((((ks << 1) | b_chi) ^ bx) << 4);
#pragma unroll
            for (int mi = 0; mi < 4; mi++) {
                const uint32_t ad = st + arow128 + mi * 2048 + acol;
                ldmx4(Ahf[mi], ad);
                ldmx4(Alf[mi], ad + 16384);
            }
#pragma unroll
            for (int njj = 0; njj < 2; njj++) {
                const uint32_t bd = st + 32768 + brow128 + njj * 2048 + bcol;
                uint32_t t[4];
                ldmx4(t, bd);
                Bhf[njj*2][0] = t[0]; Bhf[njj*2][1] = t[1];
                Bhf[njj*2+1][0] = t[2]; Bhf[njj*2+1][1] = t[3];
                ldmx4(t, bd + 16384);
                Blf[njj*2][0] = t[0]; Blf[njj*2][1] = t[1];
                Blf[njj*2+1][0] = t[2]; Blf[njj*2+1][1] = t[3];
            }
#pragma unroll
            for (int mi = 0; mi < 4; mi++)
#pragma unroll
                for (int nj = 0; nj < 4; nj++) {
                    mma16816(acc[mi][nj], Ahf[mi], Bhf[nj]);
                    mma16816(acc[mi][nj], Ahf[mi], Blf[nj]);
                    mma16816(acc[mi][nj], Alf[mi], Bhf[nj]);
                }
        }
    }
    __syncthreads();

    float* eps = (float*)sm;
    const int eg = lane >> 2;
    const int eco = (lane & 3) << 1;
#pragma unroll
    for (int mi = 0; mi < 4; mi++)
#pragma unroll
        for (int nj = 0; nj < 4; nj++) {
            const int row0 = warp_m + (mi << 4) + eg;
            const int col  = warp_n + (nj << 3) + eco;
            *(float2*)&eps[row0 * 136 + col] = make_float2(acc[mi][nj][0], acc[mi][nj][1]);
            *(float2*)&eps[(row0 + 8) * 136 + col] = make_float2(acc[mi][nj][2], acc[mi][nj][3]);
        }
    __syncthreads();

#pragma unroll
    for (int i = 0; i < 16; i++) {
        const int idx = tid + (i << 8);
        const int row = idx >> 5;
        const int c4  = idx & 31;
        const int n   = n0 + (c4 << 2);
        const int m   = m0 + row;
        float4 v = *(const float4*)&eps[row * 136 + (c4 << 2)];
        if (MODE == 2) {
            const float bb = bias[m];
            v.x += bb; v.y += bb; v.z += bb; v.w += bb;
        } else {
            const float4 bb = *(const float4*)&bias[n];
            v.x += bb.x; v.y += bb.y; v.z += bb.z; v.w += bb.w;
        }
        if (MODE == 0) {
            *(float4*)&C[(size_t)m * 1024 + n] = v;
        } else if (MODE == 1) {
            v.x *= oscale; v.y *= oscale; v.z *= oscale; v.w *= oscale;
            const int bq_ = m >> 11, s = m & 2047, h0 = n >> 6, d = n & 63;
            const size_t base = (((size_t)(bq_ * HH + h0)) * SS + s) * DK + d;
            uint32_t h01, l01, h23, l23;
            pack_hilo(v.x, v.y, h01, l01);
            pack_hilo(v.z, v.w, h23, l23);
            *(uint2*)&Dh[base] = make_uint2(h01, h23);
            *(uint2*)&Dl[base] = make_uint2(l01, l23);
        } else {
            const int h0 = m >> 6, d = m & 63, bq_ = n >> 11, s = n & 2047;
            const size_t base = (((size_t)(bq_ * HH + h0)) * DK + d) * SS + s;
            uint32_t h01, l01, h23, l23;
            pack_hilo(v.x, v.y, h01, l01);
            pack_hilo(v.z, v.w, h23, l23);
            *(uint2*)&Dh[base] = make_uint2(h01, h23);
            *(uint2*)&Dl[base] = make_uint2(l01, l23);
        }
    }
}

// Merged Q/K/V projection: 768 blocks. [0,256)=Q, [256,512)=K, [512,768)=V^T
__global__ void __launch_bounds__(256, 1)
proj_kernel(const float* __restrict__ bq, const float* __restrict__ bk,
            const float* __restrict__ bv)
{
    const int bid = blockIdx.x;
    if (bid < 512) {
        const int z = bid >> 8;
        const int t = bid & 255;
        const int m0 = (t >> 3) << 7;
        const int n0 = (t & 7) << 7;
        const __nv_bfloat16* Ah = g_act_hi + (size_t)z * ACT_N;
        const __nv_bfloat16* Al = g_act_lo + (size_t)z * ACT_N;
        const __nv_bfloat16* Bh = g_w_hi + (size_t)z * W_N;
        const __nv_bfloat16* Bl = g_w_lo + (size_t)z * W_N;
        if (z == 0)
            gemm_tc<1>(m0, n0, Ah, Al, Bh, Bl, bq, nullptr, g_q_hi, g_q_lo,
                       0.125f * 1.4426950408889634f);
        else
            gemm_tc<1>(m0, n0, Ah, Al, Bh, Bl, bk, nullptr, g_k_hi, g_k_lo, 1.0f);
    } else {
        const int t = bid - 512;
        const int m0 = (t >> 5) << 7;
        const int n0 = (t & 31) << 7;
        gemm_tc<2>(m0, n0, g_w_hi + 2 * W_N, g_w_lo + 2 * W_N,
                   g_act_hi + 2 * ACT_N, g_act_lo + 2 * ACT_N,
                   bv, nullptr, g_vt_hi, g_vt_lo, 1.0f);
    }
}

__global__ void __launch_bounds__(256, 1)
out_tc_kernel(const float* __restrict__ bo, float* __restrict__ out)
{
    const int m0 = blockIdx.y << 7;
    const int n0 = blockIdx.x << 7;
    gemm_tc<0>(m0, n0, g_attn_hi, g_attn_lo, g_w_hi + 3 * W_N, g_w_lo + 3 * W_N,
               bo, out, nullptr, nullptr, 1.0f);
}

// ---------------------------------------------------------------------------
// Flash attention, producer/consumer mbarrier pipeline. 288 threads:
// warps 0-7 = consumers (16 q-rows each, free-running), warp 8 = producer
// (K/V cp.async into a 4-stage ring). Consumers drift up to 3 tiles apart,
// so one warp's softmax overlaps another's MMA burst — no CTA barrier in
// the main loop. smem: [0,32K) Q hi|lo, [32K,160K) ring (Khi|Klo|Vhi|Vlo
// 8KB each per stage), [160K,+64) mbarrier pairs.
// ---------------------------------------------------------------------------
#define FLASH_RING   (32768)
#define FLASH_MBAR   (32768 + 4 * 32768)
#define FLASH_SMEM   (FLASH_MBAR + 128)

__global__ void __launch_bounds__(288, 1)
flash_mma_kernel(const int* __restrict__ mask)
{
    extern __shared__ char sm[];
    const uint32_t smb  = smem_u32(sm);
    const uint32_t ring = smb + FLASH_RING;
    const uint32_t mb   = smb + FLASH_MBAR;
    const int tid  = threadIdx.x;
    const int wid  = tid >> 5;
    const int lane = tid & 31;
    const int b = blockIdx.z, h = blockIdx.y;
    const int bh = b * HH + h;
    const int q0 = blockIdx.x << 7;

    // mbarrier init
    if (tid == 0) {
#pragma unroll
        for (int s = 0; s < 4; s++) {
            MBARRIER_INIT(mb + s * 16, 1);      // full[s]: producer
            MBARRIER_INIT(mb + s * 16 + 8, 8);  // empty[s]: 8 consumer warps
        }
    }

    // ---- stage Q (hi/lo) into persistent [0,32K)  (warps 0-7 only)
    if (tid < 256) {
        const int lr = tid >> 3;
        const int lc = tid & 7;
        const uint64_t gq0 = gmem_u64(g_q_hi + ((size_t)bh * SS + q0) * DK);
        const uint64_t gq1 = gmem_u64(g_q_lo + ((size_t)bh * SS + q0) * DK);
#pragma unroll
        for (int rs = 0; rs < 4; rs++) {
            const int row = (rs << 5) + lr;
            const uint64_t off = ((size_t)row * 64 + (lc << 3)) * 2;
            const uint32_t sa = swz((uint32_t)row * 128 + (lc << 4));
            cp16(smb + sa, gq0 + off);
            cp16(smb + 16384 + sa, gq1 + off);
        }
        CP_COMMIT(); CP_WAIT(0);
    }
    __syncthreads();   // Q staged + mbarriers initialized

    const uint64_t gkh = gmem_u64(g_k_hi + (size_t)bh * SS * DK);
    const uint64_t gkl = gmem_u64(g_k_lo + (size_t)bh * SS * DK);
    const uint64_t gvh = gmem_u64(g_vt_hi + (size_t)bh * DK * SS);
    const uint64_t gvl = gmem_u64(g_vt_lo + (size_t)bh * DK * SS);

    if (wid == 8) {
        // =================== PRODUCER ===================
        for (int t = 0; t < 32; t++) {
            const int s = t & 3;
            if (t >= 4) MBAR_WAIT(mb + s * 16 + 8, ((t >> 2) - 1) & 1);
            const uint32_t st = ring + (uint32_t)s * 32768;
            const int kv0 = t << 6;
#pragma unroll
            for (int rs = 0; rs < 2; rs++) {
                const int row = (rs << 5) + lane;
#pragma unroll
                for (int seg = 0; seg < 8; seg++) {
                    const uint32_t so = swz((uint32_t)row * 128 + (seg << 4));
                    const uint64_t koff = (((size_t)(kv0 + row)) * 64 + (seg << 3)) * 2;
                    const uint64_t voff = ((size_t)row * SS + kv0 + (seg << 3)) * 2;
                    cp16(st + so,         gkh + koff);
                    cp16(st + 8192 + so,  gkl + koff);
                    cp16(st + 16384 + so, gvh + voff);
                    cp16(st + 24576 + so, gvl + voff);
                }
            }
            CP_COMMIT();
            if (t >= 1) {
                CP_WAIT(1);   // group t-1 complete
                if (elect_one()) MBARRIER_ARRIVE(mb + ((t - 1) & 3) * 16);
            }
        }
        CP_WAIT(0);
        if (elect_one()) MBARRIER_ARRIVE(mb + 3 * 16);   // full[31&3]
        return;
    }

    // =================== CONSUMERS (warps 0-7) ===================
    const int arowA = (wid << 4) + (lane & 15);
    const int a_chi = lane >> 4;
    const int axA = arowA & 7;
    const uint32_t arowA128 = (uint32_t)arowA * 128;

    uint32_t qh[4][4], ql[4][4];
#pragma unroll
    for (int ks = 0; ks < 4; ks++) {
        const uint32_t col = (uint32_t)((((ks << 1) | a_chi) ^ axA) << 4);
        ldmx4(qh[ks], smb + arowA128 + col);
        ldmx4(ql[ks], smb + 16384 + arowA128 + col);
    }

    const int gq = lane >> 3;
    const int brl = ((gq >> 1) << 3) | (lane & 7);
    const int bchi = gq & 1;
    const int bxr = brl & 7;

    const int r0 = q0 + (wid << 4) + (lane >> 2);
    const int* mrow0 = mask + (size_t)r0 * SS;
    const int* mrow1 = mask + (size_t)(r0 + 8) * SS;
    const int cbase = (lane & 3) << 1;

    float o[8][4];
#pragma unroll
    for (int nj = 0; nj < 8; nj++)
#pragma unroll
        for (int r = 0; r < 4; r++) o[nj][r] = 0.f;
    float m0 = -3e38f, m1 = -3e38f, l0 = 0.f, l1 = 0.f;   // l lane-partial

    for (int t = 0; t < 32; t++) {
        const int s = t & 3;
        MBAR_WAIT(mb + s * 16, (t >> 2) & 1);
        const uint32_t st = ring + (uint32_t)s * 32768;
        const int kv0 = t << 6;

        // ---- S = Q K^T (3-pass split)
        float sc[8][4];
#pragma unroll
        for (int nj = 0; nj < 8; nj++)
#pragma unroll
            for (int r = 0; r < 4; r++) sc[nj][r] = 0.f;

#pragma unroll
        for (int ks = 0; ks < 4; ks++) {
            const uint32_t col = (uint32_t)((((ks << 1) | bchi) ^ bxr) << 4);
#pragma unroll
            for (int njj = 0; njj < 4; njj++) {
                const uint32_t rb = st + (uint32_t)((njj << 4) + brl) * 128 + col;
                uint32_t tH[4], tL[4];
                ldmx4(tH, rb);
                ldmx4(tL, rb + 8192);
                mma16816(sc[2*njj],   qh[ks], tH);
                mma16816(sc[2*njj],   qh[ks], tL);
                mma16816(sc[2*njj],   ql[ks], tH);
                mma16816(sc[2*njj+1], qh[ks], tH + 2);
                mma16816(sc[2*njj+1], qh[ks], tL + 2);
                mma16816(sc[2*njj+1], ql[ks], tH + 2);
            }
        }

        // ---- mask + online softmax (log2 domain, l lane-partial)
        float mx0 = -3e38f, mx1 = -3e38f;
#pragma unroll
        for (int nj = 0; nj < 8; nj++) {
            const int kc = kv0 + (nj << 3) + cbase;
            const int2 mv0 = *(const int2*)&mrow0[kc];
            const int2 mv1 = *(const int2*)&mrow1[kc];
            sc[nj][0] = mv0.x ? sc[nj][0] : -1e9f;
            sc[nj][1] = mv0.y ? sc[nj][1] : -1e9f;
            sc[nj][2] = mv1.x ? sc[nj][2] : -1e9f;
            sc[nj][3] = mv1.y ? sc[nj][3] : -1e9f;
            mx0 = fmaxf(mx0, fmaxf(sc[nj][0], sc[nj][1]));
            mx1 = fmaxf(mx1, fmaxf(sc[nj][2], sc[nj][3]));
        }
        mx0 = fmaxf(mx0, __shfl_xor_sync(0xffffffffu, mx0, 1));
        mx0 = fmaxf(mx0, __shfl_xor_sync(0xffffffffu, mx0, 2));
        mx1 = fmaxf(mx1, __shfl_xor_sync(0xffffffffu, mx1, 1));
        mx1 = fmaxf(mx1, __shfl_xor_sync(0xffffffffu, mx1, 2));

        const float mn0 = fmaxf(m0, mx0);
        const float mn1 = fmaxf(m1, mx1);
        const float a0 = ex2f(m0 - mn0);
        const float a1 = ex2f(m1 - mn1);
        m0 = mn0; m1 = mn1;

        float s0 = 0.f, s1 = 0.f;
#pragma unroll
        for (int nj = 0; nj < 8; nj++) {
            sc[nj][0] = ex2f(sc[nj][0] - mn0);
            sc[nj][1] = ex2f(sc[nj][1] - mn0);
            sc[nj][2] = ex2f(sc[nj][2] - mn1);
            sc[nj][3] = ex2f(sc[nj][3] - mn1);
            s0 += sc[nj][0] + sc[nj][1];
            s1 += sc[nj][2] + sc[nj][3];
        }
        l0 = l0 * a0 + s0;   // lane-partial; quad-reduced in epilogue
        l1 = l1 * a1 + s1;

#pragma unroll
        for (int nj = 0; nj < 8; nj++) {
            o[nj][0] *= a0; o[nj][1] *= a0;
            o[nj][2] *= a1; o[nj][3] *= a1;
        }

        // ---- O += P V (P in regs; 3-pass split)
#pragma unroll
        for (int kt = 0; kt < 4; kt++) {
            uint32_t ah[4], al[4];
            pack_hilo(sc[2*kt][0],   sc[2*kt][1],   ah[0], al[0]);
            pack_hilo(sc[2*kt][2],   sc[2*kt][3],   ah[1], al[1]);
            pack_hilo(sc[2*kt+1][0], sc[2*kt+1][1], ah[2], al[2]);
            pack_hilo(sc[2*kt+1][2], sc[2*kt+1][3], ah[3], al[3]);
            const uint32_t col = (uint32_t)((((kt << 1) | bchi) ^ bxr) << 4);
#pragma unroll
            for (int njj = 0; njj < 4; njj++) {
                const uint32_t rb = st + 16384 + (uint32_t)((njj << 4) + brl) * 128 + col;
                uint32_t vH[4], vL[4];
                ldmx4(vH, rb);
                ldmx4(vL, rb + 8192);
                mma16816(o[2*njj],   ah, vH);
                mma16816(o[2*njj],   ah, vL);
                mma16816(o[2*njj],   al, vH);
                mma16816(o[2*njj+1], ah, vH + 2);
                mma16816(o[2*njj+1], ah, vL + 2);
                mma16816(o[2*njj+1], al, vH + 2);
            }
        }

        if (elect_one()) MBARRIER_ARRIVE(mb + s * 16 + 8);  // release stage
    }

    // ---- epilogue: reduce l over quad, normalize, split hi/lo
    l0 += __shfl_xor_sync(0xffffffffu, l0, 1);
    l0 += __shfl_xor_sync(0xffffffffu, l0, 2);
    l1 += __shfl_xor_sync(0xffffffffu, l1, 1);
    l1 += __shfl_xor_sync(0xffffffffu, l1, 2);
    const float i0 = 1.0f / l0;
    const float i1 = 1.0f / l1;
    const size_t ro0 = ((size_t)(b * SS + q0 + (wid << 4) + (lane >> 2))) * DM + h * DK;
    const size_t ro1 = ro0 + (size_t)8 * DM;
#pragma unroll
    for (int nj = 0; nj < 8; nj++) {
        const int colg = (nj << 3) + cbase;
        uint32_t hi, lo;
        pack_hilo(o[nj][0] * i0, o[nj][1] * i0, hi, lo);
        *(uint32_t*)&g_attn_hi[ro0 + colg] = hi;
        *(uint32_t*)&g_attn_lo[ro0 + colg] = lo;
        pack_hilo(o[nj][2] * i1, o[nj][3] * i1, hi, lo);
        *(uint32_t*)&g_attn_hi[ro1 + colg] = hi;
        *(uint32_t*)&g_attn_lo[ro1 + colg] = lo;
    }
}

// ---------------------------------------------------------------------------
extern "C" void kernel_launch(void* const* d_in, const int* in_sizes, int n_in,
                              void* d_out, int out_size)
{
    const float* q    = (const float*)d_in[0];
    const float* k    = (const float*)d_in[1];
    const float* v    = (const float*)d_in[2];
    const int*   mask = (const int*)  d_in[3];
    const float* wq   = (const float*)d_in[4];
    const float* bq   = (const float*)d_in[5];
    const float* wk   = (const float*)d_in[6];
    const float* bk   = (const float*)d_in[7];
    const float* wv   = (const float*)d_in[8];
    const float* bv   = (const float*)d_in[9];
    const float* wo   = (const float*)d_in[10];
    const float* bo   = (const float*)d_in[11];
    float* out = (float*)d_out;

    cudaFuncSetAttribute(proj_kernel, cudaFuncAttributeMaxDynamicSharedMemorySize, TC_SMEM);
    cudaFuncSetAttribute(out_tc_kernel, cudaFuncAttributeMaxDynamicSharedMemorySize, TC_SMEM);
    cudaFuncSetAttribute(flash_mma_kernel, cudaFuncAttributeMaxDynamicSharedMemorySize, FLASH_SMEM);

    split_kernel<<<dim3(4096, 1, 7), 256>>>(q, k, v, wq, wk, wv, wo);
    proj_kernel<<<768, 256, TC_SMEM>>>(bq, bk, bv);
    flash_mma_kernel<<<dim3(16, 16, 2), 288, FLASH_SMEM>>>(mask);
    out_tc_kernel<<<dim3(8, 32, 1), 256, TC_SMEM>>>(bo, out);
}

// round 13
// speedup vs baseline: 1.1105x; 1.1105x over previous
#include <cuda_runtime.h>
#include <cuda_bf16.h>
#include <cstdint>

#define BB 2
#define SS 2048
#define DM 1024
#define HH 16
#define DK 64

typedef unsigned long long ull;

#define ACT_N ((size_t)4096 * 1024)
#define W_N   ((size_t)1024 * 1024)

// Scratch (__device__ globals; allocation-free rule)
__device__ __align__(16) __nv_bfloat16 g_act_hi[3 * ACT_N];   // q,k,v inputs split
__device__ __align__(16) __nv_bfloat16 g_act_lo[3 * ACT_N];
__device__ __align__(16) __nv_bfloat16 g_w_hi[4 * W_N];       // wq,wk,wv,wo split
__device__ __align__(16) __nv_bfloat16 g_w_lo[4 * W_N];
__device__ __align__(16) __nv_bfloat16 g_q_hi[BB*HH*SS*DK];   // [BH][S][64] (x0.125*log2e)
__device__ __align__(16) __nv_bfloat16 g_q_lo[BB*HH*SS*DK];
__device__ __align__(16) __nv_bfloat16 g_k_hi[BB*HH*SS*DK];   // [BH][S][64]
__device__ __align__(16) __nv_bfloat16 g_k_lo[BB*HH*SS*DK];
__device__ __align__(16) __half g_vt_hi[BB*HH*SS*DK];         // [BH][64][S] V^T fp16 hi
__device__ __align__(16) __half g_vt_lo[BB*HH*SS*DK];         // fp16 residual
__device__ __align__(16) __nv_bfloat16 g_attn_hi[ACT_N];      // flash out split
__device__ __align__(16) __nv_bfloat16 g_attn_lo[ACT_N];
__device__ ull g_maskbits[SS * (SS / 64)];                    // 512 KB bit mask

// ---------------- helpers ----------------
__device__ __forceinline__ uint32_t smem_u32(const void* p) {
    uint32_t a;
    asm("{ .reg .u64 t; cvta.to.shared.u64 t, %1; cvt.u32.u64 %0, t; }"
        : "=r"(a) : "l"(p));
    return a;
}
__device__ __forceinline__ uint64_t gmem_u64(const void* p) {
    uint64_t a;
    asm("cvta.to.global.u64 %0, %1;" : "=l"(a) : "l"(p));
    return a;
}
__device__ __forceinline__ void mma16816(float* c, const uint32_t* a, const uint32_t* b) {
    asm volatile(
        "mma.sync.aligned.m16n8k16.row.col.f32.bf16.bf16.f32 "
        "{%0,%1,%2,%3}, {%4,%5,%6,%7}, {%8,%9}, {%0,%1,%2,%3};"
        : "+f"(c[0]), "+f"(c[1]), "+f"(c[2]), "+f"(c[3])
        : "r"(a[0]), "r"(a[1]), "r"(a[2]), "r"(a[3]), "r"(b[0]), "r"(b[1]));
}
__device__ __forceinline__ void mma16816f16(float* c, const uint32_t* a, const uint32_t* b) {
    asm volatile(
        "mma.sync.aligned.m16n8k16.row.col.f32.f16.f16.f32 "
        "{%0,%1,%2,%3}, {%4,%5,%6,%7}, {%8,%9}, {%0,%1,%2,%3};"
        : "+f"(c[0]), "+f"(c[1]), "+f"(c[2]), "+f"(c[3])
        : "r"(a[0]), "r"(a[1]), "r"(a[2]), "r"(a[3]), "r"(b[0]), "r"(b[1]));
}
__device__ __forceinline__ void ldmx4(uint32_t* r, uint32_t addr) {
    asm volatile("ldmatrix.sync.aligned.m8n8.x4.shared.b16 {%0,%1,%2,%3}, [%4];"
                 : "=r"(r[0]), "=r"(r[1]), "=r"(r[2]), "=r"(r[3]) : "r"(addr));
}
__device__ __forceinline__ void cp16(uint32_t saddr, uint64_t gaddr) {
    asm volatile("cp.async.cg.shared.global [%0], [%1], 16;"
                 :: "r"(saddr), "l"(gaddr) : "memory");
}
#define CP_COMMIT() asm volatile("cp.async.commit_group;" ::: "memory")
#define CP_WAIT(n)  asm volatile("cp.async.wait_group %0;" :: "n"(n) : "memory")

__device__ __forceinline__ uint32_t swz(uint32_t x) { return x ^ ((x >> 3) & 0x70); }

__device__ __forceinline__ float ex2f(float x) {
    float y; asm("ex2.approx.f32 %0, %1;" : "=f"(y) : "f"(x)); return y;
}

// pack two fp32 -> bf16x2 hi + bf16x2 residual lo
__device__ __forceinline__ void pack_hilo(float x0, float x1, uint32_t& hi, uint32_t& lo) {
    uint32_t h;
    asm("cvt.rn.bf16x2.f32 %0, %1, %2;" : "=r"(h) : "f"(x1), "f"(x0));
    const float h0 = __uint_as_float(h << 16);
    const float h1 = __uint_as_float(h & 0xffff0000u);
    uint32_t l;
    asm("cvt.rn.bf16x2.f32 %0, %1, %2;" : "=r"(l) : "f"(x1 - h1), "f"(x0 - h0));
    hi = h; lo = l;
}

// pack two fp32 -> f16x2 hi + f16x2 residual lo
__device__ __forceinline__ void pack_hilo_f16(float x0, float x1, uint32_t& hi, uint32_t& lo) {
    uint32_t h;
    asm("cvt.rn.f16x2.f32 %0, %1, %2;" : "=r"(h) : "f"(x1), "f"(x0));
    float h0, h1;
    asm("{ .reg .f16 a,b;\n\t mov.b32 {a,b}, %2;\n\t cvt.f32.f16 %0, a;\n\t cvt.f32.f16 %1, b; }"
        : "=f"(h0), "=f"(h1) : "r"(h));
    uint32_t l;
    asm("cvt.rn.f16x2.f32 %0, %1, %2;" : "=r"(l) : "f"(x1 - h1), "f"(x0 - h0));
    hi = h; lo = l;
}

// pack two fp32 -> single f16x2
__device__ __forceinline__ uint32_t pack_f16(float x0, float x1) {
    uint32_t r;
    asm("cvt.rn.f16x2.f32 %0, %1, %2;" : "=r"(r) : "f"(x1), "f"(x0));
    return r;
}

// ---------------------------------------------------------------------------
// Mask -> bit pack: 64 int32 -> one uint64. Grid: 256 blocks x 256 threads.
// ---------------------------------------------------------------------------
__global__ void __launch_bounds__(256)
mask_pack_kernel(const int* __restrict__ mask)
{
    const int w = blockIdx.x * 256 + threadIdx.x;   // 0..65535
    const int r = w >> 5, cw = w & 31;
    const int4* src = (const int4*)(mask + (size_t)r * SS + (cw << 6));
    ull bits = 0;
#pragma unroll
    for (int i = 0; i < 16; i++) {
        const int4 v = src[i];
        bits |= (ull)(v.x != 0) << (i * 4);
        bits |= (ull)(v.y != 0) << (i * 4 + 1);
        bits |= (ull)(v.z != 0) << (i * 4 + 2);
        bits |= (ull)(v.w != 0) << (i * 4 + 3);
    }
    g_maskbits[w] = bits;
}

// ---------------------------------------------------------------------------
// Split fp32 -> bf16 hi/lo.  z=0..2: q,k,v inputs ; z=3..6: wq,wk,wv,wo
// ---------------------------------------------------------------------------
__global__ void __launch_bounds__(256)
split_kernel(const float* __restrict__ q, const float* __restrict__ k,
             const float* __restrict__ v,
             const float* __restrict__ wq, const float* __restrict__ wk,
             const float* __restrict__ wv, const float* __restrict__ wo)
{
    const int z = blockIdx.z;
    const float* src;
    __nv_bfloat16 *dh, *dl;
    size_t cnt;
    if (z < 3) {
        src = (z == 0) ? q : (z == 1) ? k : v;
        dh = g_act_hi + (size_t)z * ACT_N;
        dl = g_act_lo + (size_t)z * ACT_N;
        cnt = ACT_N;
    } else {
        const int w = z - 3;
        src = (w == 0) ? wq : (w == 1) ? wk : (w == 2) ? wv : wo;
        dh = g_w_hi + (size_t)w * W_N;
        dl = g_w_lo + (size_t)w * W_N;
        cnt = W_N;
    }
    const size_t i4 = (size_t)blockIdx.x * 256 + threadIdx.x;
    if (i4 * 4 >= cnt) return;
    float4 x = ((const float4*)src)[i4];
    uint32_t h01, l01, h23, l23;
    pack_hilo(x.x, x.y, h01, l01);
    pack_hilo(x.z, x.w, h23, l23);
    *(uint2*)&dh[i4 * 4] = make_uint2(h01, h23);
    *(uint2*)&dl[i4 * 4] = make_uint2(l01, l23);
}

// ---------------------------------------------------------------------------
// HMMA split-bf16 GEMM, 3-stage cp.async pipeline (unchanged control).
// MODE 0: fp32 out. MODE 1: q/k -> bf16 hi/lo split-head, xscale.
// MODE 2: V^T -> fp16 hi/lo [BH][64][S].
// ---------------------------------------------------------------------------
#define STAGE_BYTES 65536
#define TC_SMEM (3 * STAGE_BYTES)

template <int MODE>
__device__ __forceinline__ void gemm_tc(int m0, int n0,
                                        const __nv_bfloat16* __restrict__ Ah,
                                        const __nv_bfloat16* __restrict__ Al,
                                        const __nv_bfloat16* __restrict__ Bh,
                                        const __nv_bfloat16* __restrict__ Bl,
                                        const float* __restrict__ bias,
                                        float* __restrict__ C,
                                        void* __restrict__ Dh_,
                                        void* __restrict__ Dl_,
                                        float oscale)
{
    extern __shared__ char sm[];
    const uint32_t smb = smem_u32(sm);
    const int tid  = threadIdx.x;
    const int wid  = tid >> 5;
    const int lane = tid & 31;

    const int warp_m = (wid >> 2) << 6;
    const int warp_n = (wid & 3) << 5;

    uint64_t gb[4];
    gb[0] = gmem_u64(Ah + (size_t)m0 * 1024);
    gb[1] = gmem_u64(Al + (size_t)m0 * 1024);
    gb[2] = gmem_u64(Bh + (size_t)n0 * 1024);
    gb[3] = gmem_u64(Bl + (size_t)n0 * 1024);

    const int lr = tid >> 3;
    const int lc = tid & 7;

    const int arow = warp_m + (lane & 15);
    const int a_chi = lane >> 4;
    const int ax = arow & 7;
    const uint32_t arow128 = (uint32_t)arow * 128;
    const int g = lane >> 3;
    const int brow = warp_n + ((g >> 1) << 3) + (lane & 7);
    const int b_chi = g & 1;
    const int bx = brow & 7;
    const uint32_t brow128 = (uint32_t)brow * 128;

    float acc[4][4][4];
#pragma unroll
    for (int mi = 0; mi < 4; mi++)
#pragma unroll
        for (int nj = 0; nj < 4; nj++)
#pragma unroll
            for (int r = 0; r < 4; r++) acc[mi][nj][r] = 0.f;

    auto issue_chunk = [&](int c) {
        const int k0 = c << 6;
        const uint32_t st = smb + (uint32_t)(c % 3) * STAGE_BYTES;
#pragma unroll
        for (int op = 0; op < 4; op++) {
#pragma unroll
            for (int rb = 0; rb < 4; rb++) {
                const int row = (rb << 5) + lr;
                const uint64_t ga = gb[op] + ((size_t)row * 1024 + k0 + (lc << 3)) * 2;
                const uint32_t sa = st + op * 16384 + swz((uint32_t)row * 128 + (lc << 4));
                cp16(sa, ga);
            }
        }
        CP_COMMIT();
    };

    issue_chunk(0);
    issue_chunk(1);

    for (int c = 0; c < 16; c++) {
        if (c < 15) { CP_WAIT(1); } else { CP_WAIT(0); }
        __syncthreads();
        if (c + 2 < 16) issue_chunk(c + 2);

        const uint32_t st = smb + (uint32_t)(c % 3) * STAGE_BYTES;

#pragma unroll
        for (int ks = 0; ks < 4; ks++) {
            uint32_t Ahf[4][4], Alf[4][4], Bhf[4][2], Blf[4][2];
            const uint32_t acol = (uint32_t)((((ks << 1) | a_chi) ^ ax) << 4);
            const uint32_t bcol = (uint32_t)((((ks << 1) | b_chi) ^ bx) << 4);
#pragma unroll
            for (int mi = 0; mi < 4; mi++) {
                const uint32_t ad = st + arow128 + mi * 2048 + acol;
                ldmx4(Ahf[mi], ad);
                ldmx4(Alf[mi], ad + 16384);
            }
#pragma unroll
            for (int njj = 0; njj < 2; njj++) {
                const uint32_t bd = st + 32768 + brow128 + njj * 2048 + bcol;
                uint32_t t[4];
                ldmx4(t, bd);
                Bhf[njj*2][0] = t[0]; Bhf[njj*2][1] = t[1];
                Bhf[njj*2+1][0] = t[2]; Bhf[njj*2+1][1] = t[3];
                ldmx4(t, bd + 16384);
                Blf[njj*2][0] = t[0]; Blf[njj*2][1] = t[1];
                Blf[njj*2+1][0] = t[2]; Blf[njj*2+1][1] = t[3];
            }
#pragma unroll
            for (int mi = 0; mi < 4; mi++)
#pragma unroll
                for (int nj = 0; nj < 4; nj++) {
                    mma16816(acc[mi][nj], Ahf[mi], Bhf[nj]);
                    mma16816(acc[mi][nj], Ahf[mi], Blf[nj]);
                    mma16816(acc[mi][nj], Alf[mi], Bhf[nj]);
                }
        }
    }
    __syncthreads();

    float* eps = (float*)sm;
    const int eg = lane >> 2;
    const int eco = (lane & 3) << 1;
#pragma unroll
    for (int mi = 0; mi < 4; mi++)
#pragma unroll
        for (int nj = 0; nj < 4; nj++) {
            const int row0 = warp_m + (mi << 4) + eg;
            const int col  = warp_n + (nj << 3) + eco;
            *(float2*)&eps[row0 * 136 + col] = make_float2(acc[mi][nj][0], acc[mi][nj][1]);
            *(float2*)&eps[(row0 + 8) * 136 + col] = make_float2(acc[mi][nj][2], acc[mi][nj][3]);
        }
    __syncthreads();

#pragma unroll
    for (int i = 0; i < 16; i++) {
        const int idx = tid + (i << 8);
        const int row = idx >> 5;
        const int c4  = idx & 31;
        const int n   = n0 + (c4 << 2);
        const int m   = m0 + row;
        float4 v = *(const float4*)&eps[row * 136 + (c4 << 2)];
        if (MODE == 2) {
            const float bb = bias[m];
            v.x += bb; v.y += bb; v.z += bb; v.w += bb;
        } else {
            const float4 bb = *(const float4*)&bias[n];
            v.x += bb.x; v.y += bb.y; v.z += bb.z; v.w += bb.w;
        }
        if (MODE == 0) {
            *(float4*)&C[(size_t)m * 1024 + n] = v;
        } else if (MODE == 1) {
            __nv_bfloat16* Dh = (__nv_bfloat16*)Dh_;
            __nv_bfloat16* Dl = (__nv_bfloat16*)Dl_;
            v.x *= oscale; v.y *= oscale; v.z *= oscale; v.w *= oscale;
            const int bq_ = m >> 11, s = m & 2047, h0 = n >> 6, d = n & 63;
            const size_t base = (((size_t)(bq_ * HH + h0)) * SS + s) * DK + d;
            uint32_t h01, l01, h23, l23;
            pack_hilo(v.x, v.y, h01, l01);
            pack_hilo(v.z, v.w, h23, l23);
            *(uint2*)&Dh[base] = make_uint2(h01, h23);
            *(uint2*)&Dl[base] = make_uint2(l01, l23);
        } else {
            __half* Dh = (__half*)Dh_;
            __half* Dl = (__half*)Dl_;
            const int h0 = m >> 6, d = m & 63, bq_ = n >> 11, s = n & 2047;
            const size_t base = (((size_t)(bq_ * HH + h0)) * DK + d) * SS + s;
            uint32_t h01, l01, h23, l23;
            pack_hilo_f16(v.x, v.y, h01, l01);
            pack_hilo_f16(v.z, v.w, h23, l23);
            *(uint2*)&Dh[base] = make_uint2(h01, h23);
            *(uint2*)&Dl[base] = make_uint2(l01, l23);
        }
    }
}

// Merged Q/K/V projection: 768 blocks. [0,256)=Q, [256,512)=K, [512,768)=V^T
__global__ void __launch_bounds__(256, 1)
proj_kernel(const float* __restrict__ bq, const float* __restrict__ bk,
            const float* __restrict__ bv)
{
    const int bid = blockIdx.x;
    if (bid < 512) {
        const int z = bid >> 8;
        const int t = bid & 255;
        const int m0 = (t >> 3) << 7;
        const int n0 = (t & 7) << 7;
        const __nv_bfloat16* Ah = g_act_hi + (size_t)z * ACT_N;
        const __nv_bfloat16* Al = g_act_lo + (size_t)z * ACT_N;
        const __nv_bfloat16* Bh = g_w_hi + (size_t)z * W_N;
        const __nv_bfloat16* Bl = g_w_lo + (size_t)z * W_N;
        if (z == 0)
            gemm_tc<1>(m0, n0, Ah, Al, Bh, Bl, bq, nullptr, g_q_hi, g_q_lo,
                       0.125f * 1.4426950408889634f);
        else
            gemm_tc<1>(m0, n0, Ah, Al, Bh, Bl, bk, nullptr, g_k_hi, g_k_lo, 1.0f);
    } else {
        const int t = bid - 512;
        const int m0 = (t >> 5) << 7;
        const int n0 = (t & 31) << 7;
        gemm_tc<2>(m0, n0, g_w_hi + 2 * W_N, g_w_lo + 2 * W_N,
                   g_act_hi + 2 * ACT_N, g_act_lo + 2 * ACT_N,
                   bv, nullptr, g_vt_hi, g_vt_lo, 1.0f);
    }
}

__global__ void __launch_bounds__(256, 1)
out_tc_kernel(const float* __restrict__ bo, float* __restrict__ out)
{
    const int m0 = blockIdx.y << 7;
    const int n0 = blockIdx.x << 7;
    gemm_tc<0>(m0, n0, g_attn_hi, g_attn_lo, g_w_hi + 3 * W_N, g_w_lo + 3 * W_N,
               bo, out, nullptr, nullptr, 1.0f);
}

// ---------------------------------------------------------------------------
// Flash attention, deferred-PV (r11 base). CTA = 256 threads, 128 q-rows.
// smem: [0,32K) persistent Q (hi|lo), then 4-stage ring of 32KB
// (Khi|Klo|Vhi_f16|Vlo_f16, 8KB each). Single sync/tile; issue(t+2) post-sync.
// QK: 3-pass bf16 (Q_lo frag reloaded per k-step). PV: 2-pass fp16 (P f16,
// V^T f16 hi/lo). Mask via packed bits (2 LDG.64/tile). l lane-partial.
// ---------------------------------------------------------------------------
#define FLASH_SMEM (32768 + 4 * 32768)   // 160 KB

__global__ void __launch_bounds__(256, 1)
flash_mma_kernel(const int* __restrict__ mask)
{
    extern __shared__ char sm[];
    const uint32_t smb = smem_u32(sm);
    const uint32_t ring = smb + 32768;
    const int tid  = threadIdx.x;
    const int wid  = tid >> 5;
    const int lane = tid & 31;
    const int b = blockIdx.z, h = blockIdx.y;
    const int bh = b * HH + h;
    const int q0 = blockIdx.x << 7;

    const int lr = tid >> 3;
    const int lc = tid & 7;

    // ---- stage Q (hi/lo) into persistent [0,32K)
    {
        const uint64_t gq0 = gmem_u64(g_q_hi + ((size_t)bh * SS + q0) * DK);
        const uint64_t gq1 = gmem_u64(g_q_lo + ((size_t)bh * SS + q0) * DK);
#pragma unroll
        for (int rs = 0; rs < 4; rs++) {
            const int row = (rs << 5) + lr;
            const uint64_t off = ((size_t)row * 64 + (lc << 3)) * 2;
            const uint32_t sa = swz((uint32_t)row * 128 + (lc << 4));
            cp16(smb + sa, gq0 + off);
            cp16(smb + 16384 + sa, gq1 + off);
        }
        CP_COMMIT(); CP_WAIT(0);
        __syncthreads();
    }

    // A-fragment addressing for Q
    const int arowA = (wid << 4) + (lane & 15);
    const int a_chi = lane >> 4;
    const int axA = arowA & 7;
    const uint32_t arowA128 = (uint32_t)arowA * 128;

    uint32_t qh[4][4];
#pragma unroll
    for (int ks = 0; ks < 4; ks++) {
        const uint32_t col = (uint32_t)((((ks << 1) | a_chi) ^ axA) << 4);
        ldmx4(qh[ks], smb + arowA128 + col);
    }

    const uint64_t gkh = gmem_u64(g_k_hi + (size_t)bh * SS * DK);
    const uint64_t gkl = gmem_u64(g_k_lo + (size_t)bh * SS * DK);
    const uint64_t gvh = gmem_u64(g_vt_hi + (size_t)bh * DK * SS);
    const uint64_t gvl = gmem_u64(g_vt_lo + (size_t)bh * DK * SS);

    auto issue = [&](int t) {
        const uint32_t st = ring + (uint32_t)(t & 3) * 32768;
        const int kv0 = t << 6;
#pragma unroll
        for (int rs = 0; rs < 2; rs++) {
            const int row = (rs << 5) + lr;
            const uint32_t so = swz((uint32_t)row * 128 + (lc << 4));
            const uint64_t koff = (((size_t)(kv0 + row)) * 64 + (lc << 3)) * 2;
            const uint64_t voff = ((size_t)row * SS + kv0 + (lc << 3)) * 2;
            cp16(st + so,         gkh + koff);
            cp16(st + 8192 + so,  gkl + koff);
            cp16(st + 16384 + so, gvh + voff);
            cp16(st + 24576 + so, gvl + voff);
        }
        CP_COMMIT();
    };

    issue(0);
    issue(1);

    // B-fragment addressing for K / V^T
    const int gq = lane >> 3;
    const int brl = ((gq >> 1) << 3) | (lane & 7);
    const int bchi = gq & 1;
    const int bxr = brl & 7;

    const int qrow = q0 + (wid << 4) + (lane >> 2);
    const ull* mb0 = g_maskbits + (size_t)qrow * 32;
    const ull* mb1 = mb0 + 8 * 32;
    const int cbase = (lane & 3) << 1;

    float o[8][4];
#pragma unroll
    for (int nj = 0; nj < 8; nj++)
#pragma unroll
        for (int r = 0; r < 4; r++) o[nj][r] = 0.f;
    float m0 = -3e38f, m1 = -3e38f, l0 = 0.f, l1 = 0.f;   // l lane-partial
    uint32_t pk[4][4];   // P(t-1) fp16x2 A-fragments

    auto pv_mma = [&](int tprev) {
        const uint32_t stp = ring + (uint32_t)(tprev & 3) * 32768;
#pragma unroll
        for (int kt = 0; kt < 4; kt++) {
            const uint32_t col = (uint32_t)((((kt << 1) | bchi) ^ bxr) << 4);
#pragma unroll
            for (int njj = 0; njj < 4; njj++) {
                const uint32_t rb = stp + 16384 + (uint32_t)((njj << 4) + brl) * 128 + col;
                uint32_t vH[4], vL[4];
                ldmx4(vH, rb);
                ldmx4(vL, rb + 8192);
                mma16816f16(o[2*njj],   pk[kt], vH);
                mma16816f16(o[2*njj],   pk[kt], vL);
                mma16816f16(o[2*njj+1], pk[kt], vH + 2);
                mma16816f16(o[2*njj+1], pk[kt], vL + 2);
            }
        }
    };

    for (int t = 0; t < 32; t++) {
        if (t < 31) { CP_WAIT(1); } else { CP_WAIT(0); }
        __syncthreads();
        if (t + 2 < 32) issue(t + 2);

        const uint32_t st = ring + (uint32_t)(t & 3) * 32768;

        // mask bits for this tile (early issue; L2 hit hidden under MMAs)
        const ull w0 = mb0[t];
        const ull w1 = mb1[t];

        // ---- S = Q K^T (3-pass split); Q_lo frag reloaded from smem
        float sc[8][4];
#pragma unroll
        for (int nj = 0; nj < 8; nj++)
#pragma unroll
            for (int r = 0; r < 4; r++) sc[nj][r] = 0.f;

#pragma unroll
        for (int ks = 0; ks < 4; ks++) {
            const uint32_t colA = (uint32_t)((((ks << 1) | a_chi) ^ axA) << 4);
            uint32_t qlf[4];
            ldmx4(qlf, smb + 16384 + arowA128 + colA);
            const uint32_t col = (uint32_t)((((ks << 1) | bchi) ^ bxr) << 4);
#pragma unroll
            for (int njj = 0; njj < 4; njj++) {
                const uint32_t rb = st + (uint32_t)((njj << 4) + brl) * 128 + col;
                uint32_t tH[4], tL[4];
                ldmx4(tH, rb);
                ldmx4(tL, rb + 8192);
                mma16816(sc[2*njj],   qh[ks], tH);
                mma16816(sc[2*njj],   qh[ks], tL);
                mma16816(sc[2*njj],   qlf,    tH);
                mma16816(sc[2*njj+1], qh[ks], tH + 2);
                mma16816(sc[2*njj+1], qh[ks], tL + 2);
                mma16816(sc[2*njj+1], qlf,    tH + 2);
            }
        }

        // ---- deferred PV(t-1): queued behind QK, softmax-independent
        if (t > 0) pv_mma(t - 1);

        // ---- mask (bit tests) + online softmax (log2 domain)
        float mx0 = -3e38f, mx1 = -3e38f;
#pragma unroll
        for (int nj = 0; nj < 8; nj++) {
            const int sh = (nj << 3) + cbase;
            const uint32_t b0 = (uint32_t)(w0 >> sh);
            const uint32_t b1 = (uint32_t)(w1 >> sh);
            sc[nj][0] = (b0 & 1) ? sc[nj][0] : -1e9f;
            sc[nj][1] = (b0 & 2) ? sc[nj][1] : -1e9f;
            sc[nj][2] = (b1 & 1) ? sc[nj][2] : -1e9f;
            sc[nj][3] = (b1 & 2) ? sc[nj][3] : -1e9f;
            mx0 = fmaxf(mx0, fmaxf(sc[nj][0], sc[nj][1]));
            mx1 = fmaxf(mx1, fmaxf(sc[nj][2], sc[nj][3]));
        }
        mx0 = fmaxf(mx0, __shfl_xor_sync(0xffffffffu, mx0, 1));
        mx0 = fmaxf(mx0, __shfl_xor_sync(0xffffffffu, mx0, 2));
        mx1 = fmaxf(mx1, __shfl_xor_sync(0xffffffffu, mx1, 1));
        mx1 = fmaxf(mx1, __shfl_xor_sync(0xffffffffu, mx1, 2));

        const float mn0 = fmaxf(m0, mx0);
        const float mn1 = fmaxf(m1, mx1);
        const float a0 = ex2f(m0 - mn0);
        const float a1 = ex2f(m1 - mn1);
        m0 = mn0; m1 = mn1;

        float s0 = 0.f, s1 = 0.f;
#pragma unroll
        for (int nj = 0; nj < 8; nj++) {
            sc[nj][0] = ex2f(sc[nj][0] - mn0);
            sc[nj][1] = ex2f(sc[nj][1] - mn0);
            sc[nj][2] = ex2f(sc[nj][2] - mn1);
            sc[nj][3] = ex2f(sc[nj][3] - mn1);
            s0 += sc[nj][0] + sc[nj][1];
            s1 += sc[nj][2] + sc[nj][3];
        }
        l0 = l0 * a0 + s0;   // lane-partial; quad-reduced in epilogue
        l1 = l1 * a1 + s1;

        // pack P(t) fp16 for next iteration's PV
#pragma unroll
        for (int kt = 0; kt < 4; kt++) {
            pk[kt][0] = pack_f16(sc[2*kt][0],   sc[2*kt][1]);
            pk[kt][1] = pack_f16(sc[2*kt][2],   sc[2*kt][3]);
            pk[kt][2] = pack_f16(sc[2*kt+1][0], sc[2*kt+1][1]);
            pk[kt][3] = pack_f16(sc[2*kt+1][2], sc[2*kt+1][3]);
        }

        // O *= alpha (scoreboard-ordered after PV(t-1) lands)
#pragma unroll
        for (int nj = 0; nj < 8; nj++) {
            o[nj][0] *= a0; o[nj][1] *= a0;
            o[nj][2] *= a1; o[nj][3] *= a1;
        }
    }

    // final PV(31)
    pv_mma(31);

    // ---- epilogue: quad-reduce l, normalize, split hi/lo
    l0 += __shfl_xor_sync(0xffffffffu, l0, 1);
    l0 += __shfl_xor_sync(0xffffffffu, l0, 2);
    l1 += __shfl_xor_sync(0xffffffffu, l1, 1);
    l1 += __shfl_xor_sync(0xffffffffu, l1, 2);
    const float i0 = 1.0f / l0;
    const float i1 = 1.0f / l1;
    const size_t ro0 = ((size_t)(b * SS + q0 + (wid << 4) + (lane >> 2))) * DM + h * DK;
    const size_t ro1 = ro0 + (size_t)8 * DM;
#pragma unroll
    for (int nj = 0; nj < 8; nj++) {
        const int colg = (nj << 3) + cbase;
        uint32_t hi, lo;
        pack_hilo(o[nj][0] * i0, o[nj][1] * i0, hi, lo);
        *(uint32_t*)&g_attn_hi[ro0 + colg] = hi;
        *(uint32_t*)&g_attn_lo[ro0 + colg] = lo;
        pack_hilo(o[nj][2] * i1, o[nj][3] * i1, hi, lo);
        *(uint32_t*)&g_attn_hi[ro1 + colg] = hi;
        *(uint32_t*)&g_attn_lo[ro1 + colg] = lo;
    }
}

// ---------------------------------------------------------------------------
extern "C" void kernel_launch(void* const* d_in, const int* in_sizes, int n_in,
                              void* d_out, int out_size)
{
    const float* q    = (const float*)d_in[0];
    const float* k    = (const float*)d_in[1];
    const float* v    = (const float*)d_in[2];
    const int*   mask = (const int*)  d_in[3];
    const float* wq   = (const float*)d_in[4];
    const float* bq   = (const float*)d_in[5];
    const float* wk   = (const float*)d_in[6];
    const float* bk   = (const float*)d_in[7];
    const float* wv   = (const float*)d_in[8];
    const float* bv   = (const float*)d_in[9];
    const float* wo   = (const float*)d_in[10];
    const float* bo   = (const float*)d_in[11];
    float* out = (float*)d_out;

    cudaFuncSetAttribute(proj_kernel, cudaFuncAttributeMaxDynamicSharedMemorySize, TC_SMEM);
    cudaFuncSetAttribute(out_tc_kernel, cudaFuncAttributeMaxDynamicSharedMemorySize, TC_SMEM);
    cudaFuncSetAttribute(flash_mma_kernel, cudaFuncAttributeMaxDynamicSharedMemorySize, FLASH_SMEM);

    split_kernel<<<dim3(4096, 1, 7), 256>>>(q, k, v, wq, wk, wv, wo);
    mask_pack_kernel<<<256, 256>>>(mask);
    proj_kernel<<<768, 256, TC_SMEM>>>(bq, bk, bv);
    flash_mma_kernel<<<dim3(16, 16, 2), 256, FLASH_SMEM>>>(mask);
    out_tc_kernel<<<dim3(8, 32, 1), 256, TC_SMEM>>>(bo, out);
}

// round 14
// speedup vs baseline: 1.1794x; 1.0620x over previous
#include <cuda_runtime.h>
#include <cuda_bf16.h>
#include <cstdint>

#define BB 2
#define SS 2048
#define DM 1024
#define HH 16
#define DK 64

typedef unsigned long long ull;

#define ACT_N ((size_t)4096 * 1024)
#define W_N   ((size_t)1024 * 1024)

// Scratch (__device__ globals; allocation-free rule)
__device__ __align__(16) __nv_bfloat16 g_act_hi[3 * ACT_N];   // q,k,v inputs split
__device__ __align__(16) __nv_bfloat16 g_act_lo[3 * ACT_N];
__device__ __align__(16) __nv_bfloat16 g_w_hi[4 * W_N];       // wq,wk,wv,wo split
__device__ __align__(16) __nv_bfloat16 g_w_lo[4 * W_N];
__device__ __align__(16) __nv_bfloat16 g_q_hi[BB*HH*SS*DK];   // [BH][S][64] (x0.125*log2e)
__device__ __align__(16) __nv_bfloat16 g_q_lo[BB*HH*SS*DK];
__device__ __align__(16) __nv_bfloat16 g_k_hi[BB*HH*SS*DK];   // [BH][S][64]
__device__ __align__(16) __nv_bfloat16 g_k_lo[BB*HH*SS*DK];
__device__ __align__(16) __half g_vt_hi[BB*HH*SS*DK];         // [BH][64][S] V^T fp16 hi
__device__ __align__(16) __half g_vt_lo[BB*HH*SS*DK];         // fp16 residual
__device__ __align__(16) __nv_bfloat16 g_attn_hi[ACT_N];      // flash out split
__device__ __align__(16) __nv_bfloat16 g_attn_lo[ACT_N];
__device__ ull g_maskbits[SS * (SS / 64)];                    // 512 KB bit mask

// ---------------- helpers ----------------
__device__ __forceinline__ uint32_t smem_u32(const void* p) {
    uint32_t a;
    asm("{ .reg .u64 t; cvta.to.shared.u64 t, %1; cvt.u32.u64 %0, t; }"
        : "=r"(a) : "l"(p));
    return a;
}
__device__ __forceinline__ uint64_t gmem_u64(const void* p) {
    uint64_t a;
    asm("cvta.to.global.u64 %0, %1;" : "=l"(a) : "l"(p));
    return a;
}
__device__ __forceinline__ void mma16816(float* c, const uint32_t* a, const uint32_t* b) {
    asm volatile(
        "mma.sync.aligned.m16n8k16.row.col.f32.bf16.bf16.f32 "
        "{%0,%1,%2,%3}, {%4,%5,%6,%7}, {%8,%9}, {%0,%1,%2,%3};"
        : "+f"(c[0]), "+f"(c[1]), "+f"(c[2]), "+f"(c[3])
        : "r"(a[0]), "r"(a[1]), "r"(a[2]), "r"(a[3]), "r"(b[0]), "r"(b[1]));
}
__device__ __forceinline__ void mma16816f16(float* c, const uint32_t* a, const uint32_t* b) {
    asm volatile(
        "mma.sync.aligned.m16n8k16.row.col.f32.f16.f16.f32 "
        "{%0,%1,%2,%3}, {%4,%5,%6,%7}, {%8,%9}, {%0,%1,%2,%3};"
        : "+f"(c[0]), "+f"(c[1]), "+f"(c[2]), "+f"(c[3])
        : "r"(a[0]), "r"(a[1]), "r"(a[2]), "r"(a[3]), "r"(b[0]), "r"(b[1]));
}
__device__ __forceinline__ void ldmx4(uint32_t* r, uint32_t addr) {
    asm volatile("ldmatrix.sync.aligned.m8n8.x4.shared.b16 {%0,%1,%2,%3}, [%4];"
                 : "=r"(r[0]), "=r"(r[1]), "=r"(r[2]), "=r"(r[3]) : "r"(addr));
}
__device__ __forceinline__ void cp16(uint32_t saddr, uint64_t gaddr) {
    asm volatile("cp.async.cg.shared.global [%0], [%1], 16;"
                 :: "r"(saddr), "l"(gaddr) : "memory");
}
#define CP_COMMIT() asm volatile("cp.async.commit_group;" ::: "memory")
#define CP_WAIT(n)  asm volatile("cp.async.wait_group %0;" :: "n"(n) : "memory")

__device__ __forceinline__ uint32_t swz(uint32_t x) { return x ^ ((x >> 3) & 0x70); }

__device__ __forceinline__ float ex2f(float x) {
    float y; asm("ex2.approx.f32 %0, %1;" : "=f"(y) : "f"(x)); return y;
}

// pack two fp32 -> bf16x2 hi + bf16x2 residual lo
__device__ __forceinline__ void pack_hilo(float x0, float x1, uint32_t& hi, uint32_t& lo) {
    uint32_t h;
    asm("cvt.rn.bf16x2.f32 %0, %1, %2;" : "=r"(h) : "f"(x1), "f"(x0));
    const float h0 = __uint_as_float(h << 16);
    const float h1 = __uint_as_float(h & 0xffff0000u);
    uint32_t l;
    asm("cvt.rn.bf16x2.f32 %0, %1, %2;" : "=r"(l) : "f"(x1 - h1), "f"(x0 - h0));
    hi = h; lo = l;
}

// pack two fp32 -> f16x2 hi + f16x2 residual lo
__device__ __forceinline__ void pack_hilo_f16(float x0, float x1, uint32_t& hi, uint32_t& lo) {
    uint32_t h;
    asm("cvt.rn.f16x2.f32 %0, %1, %2;" : "=r"(h) : "f"(x1), "f"(x0));
    float h0, h1;
    asm("{ .reg .f16 a,b;\n\t mov.b32 {a,b}, %2;\n\t cvt.f32.f16 %0, a;\n\t cvt.f32.f16 %1, b; }"
        : "=f"(h0), "=f"(h1) : "r"(h));
    uint32_t l;
    asm("cvt.rn.f16x2.f32 %0, %1, %2;" : "=r"(l) : "f"(x1 - h1), "f"(x0 - h0));
    hi = h; lo = l;
}

// pack two fp32 -> single f16x2
__device__ __forceinline__ uint32_t pack_f16(float x0, float x1) {
    uint32_t r;
    asm("cvt.rn.f16x2.f32 %0, %1, %2;" : "=r"(r) : "f"(x1), "f"(x0));
    return r;
}

// ---------------------------------------------------------------------------
// Mask -> bit pack: 64 int32 -> one uint64. Grid: 256 blocks x 256 threads.
// ---------------------------------------------------------------------------
__global__ void __launch_bounds__(256)
mask_pack_kernel(const int* __restrict__ mask)
{
    const int w = blockIdx.x * 256 + threadIdx.x;   // 0..65535
    const int r = w >> 5, cw = w & 31;
    const int4* src = (const int4*)(mask + (size_t)r * SS + (cw << 6));
    ull bits = 0;
#pragma unroll
    for (int i = 0; i < 16; i++) {
        const int4 v = src[i];
        bits |= (ull)(v.x != 0) << (i * 4);
        bits |= (ull)(v.y != 0) << (i * 4 + 1);
        bits |= (ull)(v.z != 0) << (i * 4 + 2);
        bits |= (ull)(v.w != 0) << (i * 4 + 3);
    }
    g_maskbits[w] = bits;
}

// ---------------------------------------------------------------------------
// Split fp32 -> bf16 hi/lo.  z=0..2: q,k,v inputs ; z=3..6: wq,wk,wv,wo
// ---------------------------------------------------------------------------
__global__ void __launch_bounds__(256)
split_kernel(const float* __restrict__ q, const float* __restrict__ k,
             const float* __restrict__ v,
             const float* __restrict__ wq, const float* __restrict__ wk,
             const float* __restrict__ wv, const float* __restrict__ wo)
{
    const int z = blockIdx.z;
    const float* src;
    __nv_bfloat16 *dh, *dl;
    size_t cnt;
    if (z < 3) {
        src = (z == 0) ? q : (z == 1) ? k : v;
        dh = g_act_hi + (size_t)z * ACT_N;
        dl = g_act_lo + (size_t)z * ACT_N;
        cnt = ACT_N;
    } else {
        const int w = z - 3;
        src = (w == 0) ? wq : (w == 1) ? wk : (w == 2) ? wv : wo;
        dh = g_w_hi + (size_t)w * W_N;
        dl = g_w_lo + (size_t)w * W_N;
        cnt = W_N;
    }
    const size_t i4 = (size_t)blockIdx.x * 256 + threadIdx.x;
    if (i4 * 4 >= cnt) return;
    float4 x = ((const float4*)src)[i4];
    uint32_t h01, l01, h23, l23;
    pack_hilo(x.x, x.y, h01, l01);
    pack_hilo(x.z, x.w, h23, l23);
    *(uint2*)&dh[i4 * 4] = make_uint2(h01, h23);
    *(uint2*)&dl[i4 * 4] = make_uint2(l01, l23);
}

// ---------------------------------------------------------------------------
// HMMA split-bf16 GEMM, 3-stage cp.async pipeline (unchanged control).
// MODE 0: fp32 out. MODE 1: q/k -> bf16 hi/lo split-head, xscale.
// MODE 2: V^T -> fp16 hi/lo [BH][64][S].
// ---------------------------------------------------------------------------
#define STAGE_BYTES 65536
#define TC_SMEM (3 * STAGE_BYTES)

template <int MODE>
__device__ __forceinline__ void gemm_tc(int m0, int n0,
                                        const __nv_bfloat16* __restrict__ Ah,
                                        const __nv_bfloat16* __restrict__ Al,
                                        const __nv_bfloat16* __restrict__ Bh,
                                        const __nv_bfloat16* __restrict__ Bl,
                                        const float* __restrict__ bias,
                                        float* __restrict__ C,
                                        void* __restrict__ Dh_,
                                        void* __restrict__ Dl_,
                                        float oscale)
{
    extern __shared__ char sm[];
    const uint32_t smb = smem_u32(sm);
    const int tid  = threadIdx.x;
    const int wid  = tid >> 5;
    const int lane = tid & 31;

    const int warp_m = (wid >> 2) << 6;
    const int warp_n = (wid & 3) << 5;

    uint64_t gb[4];
    gb[0] = gmem_u64(Ah + (size_t)m0 * 1024);
    gb[1] = gmem_u64(Al + (size_t)m0 * 1024);
    gb[2] = gmem_u64(Bh + (size_t)n0 * 1024);
    gb[3] = gmem_u64(Bl + (size_t)n0 * 1024);

    const int lr = tid >> 3;
    const int lc = tid & 7;

    const int arow = warp_m + (lane & 15);
    const int a_chi = lane >> 4;
    const int ax = arow & 7;
    const uint32_t arow128 = (uint32_t)arow * 128;
    const int g = lane >> 3;
    const int brow = warp_n + ((g >> 1) << 3) + (lane & 7);
    const int b_chi = g & 1;
    const int bx = brow & 7;
    const uint32_t brow128 = (uint32_t)brow * 128;

    float acc[4][4][4];
#pragma unroll
    for (int mi = 0; mi < 4; mi++)
#pragma unroll
        for (int nj = 0; nj < 4; nj++)
#pragma unroll
            for (int r = 0; r < 4; r++) acc[mi][nj][r] = 0.f;

    auto issue_chunk = [&](int c) {
        const int k0 = c << 6;
        const uint32_t st = smb + (uint32_t)(c % 3) * STAGE_BYTES;
#pragma unroll
        for (int op = 0; op < 4; op++) {
#pragma unroll
            for (int rb = 0; rb < 4; rb++) {
                const int row = (rb << 5) + lr;
                const uint64_t ga = gb[op] + ((size_t)row * 1024 + k0 + (lc << 3)) * 2;
                const uint32_t sa = st + op * 16384 + swz((uint32_t)row * 128 + (lc << 4));
                cp16(sa, ga);
            }
        }
        CP_COMMIT();
    };

    issue_chunk(0);
    issue_chunk(1);

    for (int c = 0; c < 16; c++) {
        if (c < 15) { CP_WAIT(1); } else { CP_WAIT(0); }
        __syncthreads();
        if (c + 2 < 16) issue_chunk(c + 2);

        const uint32_t st = smb + (uint32_t)(c % 3) * STAGE_BYTES;

#pragma unroll
        for (int ks = 0; ks < 4; ks++) {
            uint32_t Ahf[4][4], Alf[4][4], Bhf[4][2], Blf[4][2];
            const uint32_t acol = (uint32_t)((((ks << 1) | a_chi) ^ ax) << 4);
            const uint32_t bcol = (uint32_t)((((ks << 1) | b_chi) ^ bx) << 4);
#pragma unroll
            for (int mi = 0; mi < 4; mi++) {
                const uint32_t ad = st + arow128 + mi * 2048 + acol;
                ldmx4(Ahf[mi], ad);
                ldmx4(Alf[mi], ad + 16384);
            }
#pragma unroll
            for (int njj = 0; njj < 2; njj++) {
                const uint32_t bd = st + 32768 + brow128 + njj * 2048 + bcol;
                uint32_t t[4];
                ldmx4(t, bd);
                Bhf[njj*2][0] = t[0]; Bhf[njj*2][1] = t[1];
                Bhf[njj*2+1][0] = t[2]; Bhf[njj*2+1][1] = t[3];
                ldmx4(t, bd + 16384);
                Blf[njj*2][0] = t[0]; Blf[njj*2][1] = t[1];
                Blf[njj*2+1][0] = t[2]; Blf[njj*2+1][1] = t[3];
            }
#pragma unroll
            for (int mi = 0; mi < 4; mi++)
#pragma unroll
                for (int nj = 0; nj < 4; nj++) {
                    mma16816(acc[mi][nj], Ahf[mi], Bhf[nj]);
                    mma16816(acc[mi][nj], Ahf[mi], Blf[nj]);
                    mma16816(acc[mi][nj], Alf[mi], Bhf[nj]);
                }
        }
    }
    __syncthreads();

    float* eps = (float*)sm;
    const int eg = lane >> 2;
    const int eco = (lane & 3) << 1;
#pragma unroll
    for (int mi = 0; mi < 4; mi++)
#pragma unroll
        for (int nj = 0; nj < 4; nj++) {
            const int row0 = warp_m + (mi << 4) + eg;
            const int col  = warp_n + (nj << 3) + eco;
            *(float2*)&eps[row0 * 136 + col] = make_float2(acc[mi][nj][0], acc[mi][nj][1]);
            *(float2*)&eps[(row0 + 8) * 136 + col] = make_float2(acc[mi][nj][2], acc[mi][nj][3]);
        }
    __syncthreads();

#pragma unroll
    for (int i = 0; i < 16; i++) {
        const int idx = tid + (i << 8);
        const int row = idx >> 5;
        const int c4  = idx & 31;
        const int n   = n0 + (c4 << 2);
        const int m   = m0 + row;
        float4 v = *(const float4*)&eps[row * 136 + (c4 << 2)];
        if (MODE == 2) {
            const float bb = bias[m];
            v.x += bb; v.y += bb; v.z += bb; v.w += bb;
        } else {
            const float4 bb = *(const float4*)&bias[n];
            v.x += bb.x; v.y += bb.y; v.z += bb.z; v.w += bb.w;
        }
        if (MODE == 0) {
            *(float4*)&C[(size_t)m * 1024 + n] = v;
        } else if (MODE == 1) {
            __nv_bfloat16* Dh = (__nv_bfloat16*)Dh_;
            __nv_bfloat16* Dl = (__nv_bfloat16*)Dl_;
            v.x *= oscale; v.y *= oscale; v.z *= oscale; v.w *= oscale;
            const int bq_ = m >> 11, s = m & 2047, h0 = n >> 6, d = n & 63;
            const size_t base = (((size_t)(bq_ * HH + h0)) * SS + s) * DK + d;
            uint32_t h01, l01, h23, l23;
            pack_hilo(v.x, v.y, h01, l01);
            pack_hilo(v.z, v.w, h23, l23);
            *(uint2*)&Dh[base] = make_uint2(h01, h23);
            *(uint2*)&Dl[base] = make_uint2(l01, l23);
        } else {
            __half* Dh = (__half*)Dh_;
            __half* Dl = (__half*)Dl_;
            const int h0 = m >> 6, d = m & 63, bq_ = n >> 11, s = n & 2047;
            const size_t base = (((size_t)(bq_ * HH + h0)) * DK + d) * SS + s;
            uint32_t h01, l01, h23, l23;
            pack_hilo_f16(v.x, v.y, h01, l01);
            pack_hilo_f16(v.z, v.w, h23, l23);
            *(uint2*)&Dh[base] = make_uint2(h01, h23);
            *(uint2*)&Dl[base] = make_uint2(l01, l23);
        }
    }
}

// Merged Q/K/V projection: 768 blocks. [0,256)=Q, [256,512)=K, [512,768)=V^T
__global__ void __launch_bounds__(256, 1)
proj_kernel(const float* __restrict__ bq, const float* __restrict__ bk,
            const float* __restrict__ bv)
{
    const int bid = blockIdx.x;
    if (bid < 512) {
        const int z = bid >> 8;
        const int t = bid & 255;
        const int m0 = (t >> 3) << 7;
        const int n0 = (t & 7) << 7;
        const __nv_bfloat16* Ah = g_act_hi + (size_t)z * ACT_N;
        const __nv_bfloat16* Al = g_act_lo + (size_t)z * ACT_N;
        const __nv_bfloat16* Bh = g_w_hi + (size_t)z * W_N;
        const __nv_bfloat16* Bl = g_w_lo + (size_t)z * W_N;
        if (z == 0)
            gemm_tc<1>(m0, n0, Ah, Al, Bh, Bl, bq, nullptr, g_q_hi, g_q_lo,
                       0.125f * 1.4426950408889634f);
        else
            gemm_tc<1>(m0, n0, Ah, Al, Bh, Bl, bk, nullptr, g_k_hi, g_k_lo, 1.0f);
    } else {
        const int t = bid - 512;
        const int m0 = (t >> 5) << 7;
        const int n0 = (t & 31) << 7;
        gemm_tc<2>(m0, n0, g_w_hi + 2 * W_N, g_w_lo + 2 * W_N,
                   g_act_hi + 2 * ACT_N, g_act_lo + 2 * ACT_N,
                   bv, nullptr, g_vt_hi, g_vt_lo, 1.0f);
    }
}

__global__ void __launch_bounds__(256, 1)
out_tc_kernel(const float* __restrict__ bo, float* __restrict__ out)
{
    const int m0 = blockIdx.y << 7;
    const int n0 = blockIdx.x << 7;
    gemm_tc<0>(m0, n0, g_attn_hi, g_attn_lo, g_w_hi + 3 * W_N, g_w_lo + 3 * W_N,
               bo, out, nullptr, nullptr, 1.0f);
}

// ---------------------------------------------------------------------------
// Flash attention, 2 CTAs/SM. CTA = 256 threads, 128 q-rows.
// smem: [0,32K) persistent Q (hi|lo), [32K,96K) 2-stage ring
// (Khi|Klo|Vhi_f16|Vlo_f16, 8KB each). 96KB/CTA -> 2 CTAs co-resident,
// independent barrier domains overlap each other's softmax/MMA phases.
// QK: 3-pass bf16 (Q_lo frag from smem). PV: in-tile 2-pass fp16.
// Mask: packed bits. Softmax: log2 domain, ex2, lane-partial l.
// ---------------------------------------------------------------------------
#define FLASH_SMEM (32768 + 2 * 32768)   // 96 KB

__global__ void __launch_bounds__(256, 2)
flash_mma_kernel(const int* __restrict__ mask)
{
    extern __shared__ char sm[];
    const uint32_t smb = smem_u32(sm);
    const uint32_t ring = smb + 32768;
    const int tid  = threadIdx.x;
    const int wid  = tid >> 5;
    const int lane = tid & 31;
    const int b = blockIdx.z, h = blockIdx.y;
    const int bh = b * HH + h;
    const int q0 = blockIdx.x << 7;

    const int lr = tid >> 3;
    const int lc = tid & 7;

    // ---- stage Q (hi/lo) into persistent [0,32K)
    {
        const uint64_t gq0 = gmem_u64(g_q_hi + ((size_t)bh * SS + q0) * DK);
        const uint64_t gq1 = gmem_u64(g_q_lo + ((size_t)bh * SS + q0) * DK);
#pragma unroll
        for (int rs = 0; rs < 4; rs++) {
            const int row = (rs << 5) + lr;
            const uint64_t off = ((size_t)row * 64 + (lc << 3)) * 2;
            const uint32_t sa = swz((uint32_t)row * 128 + (lc << 4));
            cp16(smb + sa, gq0 + off);
            cp16(smb + 16384 + sa, gq1 + off);
        }
        CP_COMMIT(); CP_WAIT(0);
        __syncthreads();
    }

    // A-fragment addressing for Q
    const int arowA = (wid << 4) + (lane & 15);
    const int a_chi = lane >> 4;
    const int axA = arowA & 7;
    const uint32_t arowA128 = (uint32_t)arowA * 128;

    uint32_t qh[4][4];
#pragma unroll
    for (int ks = 0; ks < 4; ks++) {
        const uint32_t col = (uint32_t)((((ks << 1) | a_chi) ^ axA) << 4);
        ldmx4(qh[ks], smb + arowA128 + col);
    }

    const uint64_t gkh = gmem_u64(g_k_hi + (size_t)bh * SS * DK);
    const uint64_t gkl = gmem_u64(g_k_lo + (size_t)bh * SS * DK);
    const uint64_t gvh = gmem_u64(g_vt_hi + (size_t)bh * DK * SS);
    const uint64_t gvl = gmem_u64(g_vt_lo + (size_t)bh * DK * SS);

    auto issue = [&](int t) {
        const uint32_t st = ring + (uint32_t)(t & 1) * 32768;
        const int kv0 = t << 6;
#pragma unroll
        for (int rs = 0; rs < 2; rs++) {
            const int row = (rs << 5) + lr;
            const uint32_t so = swz((uint32_t)row * 128 + (lc << 4));
            const uint64_t koff = (((size_t)(kv0 + row)) * 64 + (lc << 3)) * 2;
            const uint64_t voff = ((size_t)row * SS + kv0 + (lc << 3)) * 2;
            cp16(st + so,         gkh + koff);
            cp16(st + 8192 + so,  gkl + koff);
            cp16(st + 16384 + so, gvh + voff);
            cp16(st + 24576 + so, gvl + voff);
        }
        CP_COMMIT();
    };

    issue(0);

    // B-fragment addressing for K / V^T
    const int gq = lane >> 3;
    const int brl = ((gq >> 1) << 3) | (lane & 7);
    const int bchi = gq & 1;
    const int bxr = brl & 7;

    const int qrow = q0 + (wid << 4) + (lane >> 2);
    const ull* mb0 = g_maskbits + (size_t)qrow * 32;
    const ull* mb1 = mb0 + 8 * 32;
    const int cbase = (lane & 3) << 1;

    float o[8][4];
#pragma unroll
    for (int nj = 0; nj < 8; nj++)
#pragma unroll
        for (int r = 0; r < 4; r++) o[nj][r] = 0.f;
    float m0 = -3e38f, m1 = -3e38f, l0 = 0.f, l1 = 0.f;   // l lane-partial

    for (int t = 0; t < 32; t++) {
        // issue next tile into the other buffer (guarded by prev end-sync)
        if (t < 31) { issue(t + 1); CP_WAIT(1); }
        else        { CP_WAIT(0); }
        __syncthreads();

        const uint32_t st = ring + (uint32_t)(t & 1) * 32768;

        // mask bits for this tile
        const ull w0 = mb0[t];
        const ull w1 = mb1[t];

        // ---- S = Q K^T (3-pass split); Q_lo frag reloaded from smem
        float sc[8][4];
#pragma unroll
        for (int nj = 0; nj < 8; nj++)
#pragma unroll
            for (int r = 0; r < 4; r++) sc[nj][r] = 0.f;

#pragma unroll
        for (int ks = 0; ks < 4; ks++) {
            const uint32_t colA = (uint32_t)((((ks << 1) | a_chi) ^ axA) << 4);
            uint32_t qlf[4];
            ldmx4(qlf, smb + 16384 + arowA128 + colA);
            const uint32_t col = (uint32_t)((((ks << 1) | bchi) ^ bxr) << 4);
#pragma unroll
            for (int njj = 0; njj < 4; njj++) {
                const uint32_t rb = st + (uint32_t)((njj << 4) + brl) * 128 + col;
                uint32_t tH[4], tL[4];
                ldmx4(tH, rb);
                ldmx4(tL, rb + 8192);
                mma16816(sc[2*njj],   qh[ks], tH);
                mma16816(sc[2*njj],   qh[ks], tL);
                mma16816(sc[2*njj],   qlf,    tH);
                mma16816(sc[2*njj+1], qh[ks], tH + 2);
                mma16816(sc[2*njj+1], qh[ks], tL + 2);
                mma16816(sc[2*njj+1], qlf,    tH + 2);
            }
        }

        // ---- mask (bit tests) + online softmax (log2 domain)
        float mx0 = -3e38f, mx1 = -3e38f;
#pragma unroll
        for (int nj = 0; nj < 8; nj++) {
            const int sh = (nj << 3) + cbase;
            const uint32_t b0 = (uint32_t)(w0 >> sh);
            const uint32_t b1 = (uint32_t)(w1 >> sh);
            sc[nj][0] = (b0 & 1) ? sc[nj][0] : -1e9f;
            sc[nj][1] = (b0 & 2) ? sc[nj][1] : -1e9f;
            sc[nj][2] = (b1 & 1) ? sc[nj][2] : -1e9f;
            sc[nj][3] = (b1 & 2) ? sc[nj][3] : -1e9f;
            mx0 = fmaxf(mx0, fmaxf(sc[nj][0], sc[nj][1]));
            mx1 = fmaxf(mx1, fmaxf(sc[nj][2], sc[nj][3]));
        }
        mx0 = fmaxf(mx0, __shfl_xor_sync(0xffffffffu, mx0, 1));
        mx0 = fmaxf(mx0, __shfl_xor_sync(0xffffffffu, mx0, 2));
        mx1 = fmaxf(mx1, __shfl_xor_sync(0xffffffffu, mx1, 1));
        mx1 = fmaxf(mx1, __shfl_xor_sync(0xffffffffu, mx1, 2));

        const float mn0 = fmaxf(m0, mx0);
        const float mn1 = fmaxf(m1, mx1);
        const float a0 = ex2f(m0 - mn0);
        const float a1 = ex2f(m1 - mn1);
        m0 = mn0; m1 = mn1;

        float s0 = 0.f, s1 = 0.f;
#pragma unroll
        for (int nj = 0; nj < 8; nj++) {
            sc[nj][0] = ex2f(sc[nj][0] - mn0);
            sc[nj][1] = ex2f(sc[nj][1] - mn0);
            sc[nj][2] = ex2f(sc[nj][2] - mn1);
            sc[nj][3] = ex2f(sc[nj][3] - mn1);
            s0 += sc[nj][0] + sc[nj][1];
            s1 += sc[nj][2] + sc[nj][3];
        }
        l0 = l0 * a0 + s0;
        l1 = l1 * a1 + s1;

        // O *= alpha before in-tile PV
#pragma unroll
        for (int nj = 0; nj < 8; nj++) {
            o[nj][0] *= a0; o[nj][1] *= a0;
            o[nj][2] *= a1; o[nj][3] *= a1;
        }

        // ---- O += P V (in-tile; P fp16, V^T fp16 hi/lo 2-pass)
#pragma unroll
        for (int kt = 0; kt < 4; kt++) {
            uint32_t pkk[4];
            pkk[0] = pack_f16(sc[2*kt][0],   sc[2*kt][1]);
            pkk[1] = pack_f16(sc[2*kt][2],   sc[2*kt][3]);
            pkk[2] = pack_f16(sc[2*kt+1][0], sc[2*kt+1][1]);
            pkk[3] = pack_f16(sc[2*kt+1][2], sc[2*kt+1][3]);
            const uint32_t col = (uint32_t)((((kt << 1) | bchi) ^ bxr) << 4);
#pragma unroll
            for (int njj = 0; njj < 4; njj++) {
                const uint32_t rb = st + 16384 + (uint32_t)((njj << 4) + brl) * 128 + col;
                uint32_t vH[4], vL[4];
                ldmx4(vH, rb);
                ldmx4(vL, rb + 8192);
                mma16816f16(o[2*njj],   pkk, vH);
                mma16816f16(o[2*njj],   pkk, vL);
                mma16816f16(o[2*njj+1], pkk, vH + 2);
                mma16816f16(o[2*njj+1], pkk, vL + 2);
            }
        }
        __syncthreads();   // all reads of stage (t&1) done before issue(t+2)
    }

    // ---- epilogue: quad-reduce l, normalize, split hi/lo
    l0 += __shfl_xor_sync(0xffffffffu, l0, 1);
    l0 += __shfl_xor_sync(0xffffffffu, l0, 2);
    l1 += __shfl_xor_sync(0xffffffffu, l1, 1);
    l1 += __shfl_xor_sync(0xffffffffu, l1, 2);
    const float i0 = 1.0f / l0;
    const float i1 = 1.0f / l1;
    const size_t ro0 = ((size_t)(b * SS + q0 + (wid << 4) + (lane >> 2))) * DM + h * DK;
    const size_t ro1 = ro0 + (size_t)8 * DM;
#pragma unroll
    for (int nj = 0; nj < 8; nj++) {
        const int colg = (nj << 3) + cbase;
        uint32_t hi, lo;
        pack_hilo(o[nj][0] * i0, o[nj][1] * i0, hi, lo);
        *(uint32_t*)&g_attn_hi[ro0 + colg] = hi;
        *(uint32_t*)&g_attn_lo[ro0 + colg] = lo;
        pack_hilo(o[nj][2] * i1, o[nj][3] * i1, hi, lo);
        *(uint32_t*)&g_attn_hi[ro1 + colg] = hi;
        *(uint32_t*)&g_attn_lo[ro1 + colg] = lo;
    }
}

// ---------------------------------------------------------------------------
extern "C" void kernel_launch(void* const* d_in, const int* in_sizes, int n_in,
                              void* d_out, int out_size)
{
    const float* q    = (const float*)d_in[0];
    const float* k    = (const float*)d_in[1];
    const float* v    = (const float*)d_in[2];
    const int*   mask = (const int*)  d_in[3];
    const float* wq   = (const float*)d_in[4];
    const float* bq   = (const float*)d_in[5];
    const float* wk   = (const float*)d_in[6];
    const float* bk   = (const float*)d_in[7];
    const float* wv   = (const float*)d_in[8];
    const float* bv   = (const float*)d_in[9];
    const float* wo   = (const float*)d_in[10];
    const float* bo   = (const float*)d_in[11];
    float* out = (float*)d_out;

    cudaFuncSetAttribute(proj_kernel, cudaFuncAttributeMaxDynamicSharedMemorySize, TC_SMEM);
    cudaFuncSetAttribute(out_tc_kernel, cudaFuncAttributeMaxDynamicSharedMemorySize, TC_SMEM);
    cudaFuncSetAttribute(flash_mma_kernel, cudaFuncAttributeMaxDynamicSharedMemorySize, FLASH_SMEM);

    split_kernel<<<dim3(4096, 1, 7), 256>>>(q, k, v, wq, wk, wv, wo);
    mask_pack_kernel<<<256, 256>>>(mask);
    proj_kernel<<<768, 256, TC_SMEM>>>(bq, bk, bv);
    flash_mma_kernel<<<dim3(16, 16, 2), 256, FLASH_SMEM>>>(mask);
    out_tc_kernel<<<dim3(8, 32, 1), 256, TC_SMEM>>>(bo, out);
}

// round 15
// speedup vs baseline: 1.3781x; 1.1684x over previous
#include <cuda_runtime.h>
#include <cuda_bf16.h>
#include <cuda_fp16.h>
#include <cstdint>

#define BB 2
#define SS 2048
#define DM 1024
#define HH 16
#define DK 64

typedef unsigned long long ull;

#define ACT_N ((size_t)4096 * 1024)
#define W_N   ((size_t)1024 * 1024)

// Scratch (__device__ globals; allocation-free rule)
__device__ __align__(16) __nv_bfloat16 g_act_hi[3 * ACT_N];   // q,k,v inputs split
__device__ __align__(16) __nv_bfloat16 g_act_lo[3 * ACT_N];
__device__ __align__(16) __nv_bfloat16 g_w_hi[4 * W_N];       // wq,wk,wv,wo split
__device__ __align__(16) __nv_bfloat16 g_w_lo[4 * W_N];
__device__ __align__(16) __half g_q16[BB*HH*SS*DK];           // [BH][S][64] fp16 (x0.125*log2e)
__device__ __align__(16) __half g_k16[BB*HH*SS*DK];           // [BH][S][64] fp16
__device__ __align__(16) __half g_vt_hi[BB*HH*SS*DK];         // [BH][64][S] V^T fp16 hi
__device__ __align__(16) __half g_vt_lo[BB*HH*SS*DK];         // fp16 residual
__device__ __align__(16) __nv_bfloat16 g_attn_hi[ACT_N];      // flash out split
__device__ __align__(16) __nv_bfloat16 g_attn_lo[ACT_N];
__device__ ull g_maskbits[SS * (SS / 64)];                    // 512 KB bit mask

// ---------------- helpers ----------------
__device__ __forceinline__ uint32_t smem_u32(const void* p) {
    uint32_t a;
    asm("{ .reg .u64 t; cvta.to.shared.u64 t, %1; cvt.u32.u64 %0, t; }"
        : "=r"(a) : "l"(p));
    return a;
}
__device__ __forceinline__ uint64_t gmem_u64(const void* p) {
    uint64_t a;
    asm("cvta.to.global.u64 %0, %1;" : "=l"(a) : "l"(p));
    return a;
}
__device__ __forceinline__ void mma16816(float* c, const uint32_t* a, const uint32_t* b) {
    asm volatile(
        "mma.sync.aligned.m16n8k16.row.col.f32.bf16.bf16.f32 "
        "{%0,%1,%2,%3}, {%4,%5,%6,%7}, {%8,%9}, {%0,%1,%2,%3};"
        : "+f"(c[0]), "+f"(c[1]), "+f"(c[2]), "+f"(c[3])
        : "r"(a[0]), "r"(a[1]), "r"(a[2]), "r"(a[3]), "r"(b[0]), "r"(b[1]));
}
__device__ __forceinline__ void mma16816f16(float* c, const uint32_t* a, const uint32_t* b) {
    asm volatile(
        "mma.sync.aligned.m16n8k16.row.col.f32.f16.f16.f32 "
        "{%0,%1,%2,%3}, {%4,%5,%6,%7}, {%8,%9}, {%0,%1,%2,%3};"
        : "+f"(c[0]), "+f"(c[1]), "+f"(c[2]), "+f"(c[3])
        : "r"(a[0]), "r"(a[1]), "r"(a[2]), "r"(a[3]), "r"(b[0]), "r"(b[1]));
}
__device__ __forceinline__ void ldmx4(uint32_t* r, uint32_t addr) {
    asm volatile("ldmatrix.sync.aligned.m8n8.x4.shared.b16 {%0,%1,%2,%3}, [%4];"
                 : "=r"(r[0]), "=r"(r[1]), "=r"(r[2]), "=r"(r[3]) : "r"(addr));
}
__device__ __forceinline__ void cp16(uint32_t saddr, uint64_t gaddr) {
    asm volatile("cp.async.cg.shared.global [%0], [%1], 16;"
                 :: "r"(saddr), "l"(gaddr) : "memory");
}
#define CP_COMMIT() asm volatile("cp.async.commit_group;" ::: "memory")
#define CP_WAIT(n)  asm volatile("cp.async.wait_group %0;" :: "n"(n) : "memory")

__device__ __forceinline__ uint32_t swz(uint32_t x) { return x ^ ((x >> 3) & 0x70); }

__device__ __forceinline__ float ex2f(float x) {
    float y; asm("ex2.approx.f32 %0, %1;" : "=f"(y) : "f"(x)); return y;
}

// pack two fp32 -> bf16x2 hi + bf16x2 residual lo
__device__ __forceinline__ void pack_hilo(float x0, float x1, uint32_t& hi, uint32_t& lo) {
    uint32_t h;
    asm("cvt.rn.bf16x2.f32 %0, %1, %2;" : "=r"(h) : "f"(x1), "f"(x0));
    const float h0 = __uint_as_float(h << 16);
    const float h1 = __uint_as_float(h & 0xffff0000u);
    uint32_t l;
    asm("cvt.rn.bf16x2.f32 %0, %1, %2;" : "=r"(l) : "f"(x1 - h1), "f"(x0 - h0));
    hi = h; lo = l;
}

// pack two fp32 -> f16x2 hi + f16x2 residual lo
__device__ __forceinline__ void pack_hilo_f16(float x0, float x1, uint32_t& hi, uint32_t& lo) {
    uint32_t h;
    asm("cvt.rn.f16x2.f32 %0, %1, %2;" : "=r"(h) : "f"(x1), "f"(x0));
    float h0, h1;
    asm("{ .reg .f16 a,b;\n\t mov.b32 {a,b}, %2;\n\t cvt.f32.f16 %0, a;\n\t cvt.f32.f16 %1, b; }"
        : "=f"(h0), "=f"(h1) : "r"(h));
    uint32_t l;
    asm("cvt.rn.f16x2.f32 %0, %1, %2;" : "=r"(l) : "f"(x1 - h1), "f"(x0 - h0));
    hi = h; lo = l;
}

// pack two fp32 -> single f16x2
__device__ __forceinline__ uint32_t pack_f16(float x0, float x1) {
    uint32_t r;
    asm("cvt.rn.f16x2.f32 %0, %1, %2;" : "=r"(r) : "f"(x1), "f"(x0));
    return r;
}

// ---------------------------------------------------------------------------
// Mask -> bit pack: 64 int32 -> one uint64.
// ---------------------------------------------------------------------------
__global__ void __launch_bounds__(256)
mask_pack_kernel(const int* __restrict__ mask)
{
    const int w = blockIdx.x * 256 + threadIdx.x;   // 0..65535
    const int r = w >> 5, cw = w & 31;
    const int4* src = (const int4*)(mask + (size_t)r * SS + (cw << 6));
    ull bits = 0;
#pragma unroll
    for (int i = 0; i < 16; i++) {
        const int4 v = src[i];
        bits |= (ull)(v.x != 0) << (i * 4);
        bits |= (ull)(v.y != 0) << (i * 4 + 1);
        bits |= (ull)(v.z != 0) << (i * 4 + 2);
        bits |= (ull)(v.w != 0) << (i * 4 + 3);
    }
    g_maskbits[w] = bits;
}

// ---------------------------------------------------------------------------
// Split fp32 -> bf16 hi/lo.  z=0..2: q,k,v inputs ; z=3..6: wq,wk,wv,wo
// ---------------------------------------------------------------------------
__global__ void __launch_bounds__(256)
split_kernel(const float* __restrict__ q, const float* __restrict__ k,
             const float* __restrict__ v,
             const float* __restrict__ wq, const float* __restrict__ wk,
             const float* __restrict__ wv, const float* __restrict__ wo)
{
    const int z = blockIdx.z;
    const float* src;
    __nv_bfloat16 *dh, *dl;
    size_t cnt;
    if (z < 3) {
        src = (z == 0) ? q : (z == 1) ? k : v;
        dh = g_act_hi + (size_t)z * ACT_N;
        dl = g_act_lo + (size_t)z * ACT_N;
        cnt = ACT_N;
    } else {
        const int w = z - 3;
        src = (w == 0) ? wq : (w == 1) ? wk : (w == 2) ? wv : wo;
        dh = g_w_hi + (size_t)w * W_N;
        dl = g_w_lo + (size_t)w * W_N;
        cnt = W_N;
    }
    const size_t i4 = (size_t)blockIdx.x * 256 + threadIdx.x;
    if (i4 * 4 >= cnt) return;
    float4 x = ((const float4*)src)[i4];
    uint32_t h01, l01, h23, l23;
    pack_hilo(x.x, x.y, h01, l01);
    pack_hilo(x.z, x.w, h23, l23);
    *(uint2*)&dh[i4 * 4] = make_uint2(h01, h23);
    *(uint2*)&dl[i4 * 4] = make_uint2(l01, l23);
}

// ---------------------------------------------------------------------------
// HMMA split-bf16 GEMM, 3-stage cp.async pipeline (control).
// MODE 0: fp32 out. MODE 1: q/k -> single fp16 split-head, xscale.
// MODE 2: V^T -> fp16 hi/lo [BH][64][S].
// ---------------------------------------------------------------------------
#define STAGE_BYTES 65536
#define TC_SMEM (3 * STAGE_BYTES)

template <int MODE>
__device__ __forceinline__ void gemm_tc(int m0, int n0,
                                        const __nv_bfloat16* __restrict__ Ah,
                                        const __nv_bfloat16* __restrict__ Al,
                                        const __nv_bfloat16* __restrict__ Bh,
                                        const __nv_bfloat16* __restrict__ Bl,
                                        const float* __restrict__ bias,
                                        float* __restrict__ C,
                                        void* __restrict__ Dh_,
                                        void* __restrict__ Dl_,
                                        float oscale)
{
    extern __shared__ char sm[];
    const uint32_t smb = smem_u32(sm);
    const int tid  = threadIdx.x;
    const int wid  = tid >> 5;
    const int lane = tid & 31;

    const int warp_m = (wid >> 2) << 6;
    const int warp_n = (wid & 3) << 5;

    uint64_t gb[4];
    gb[0] = gmem_u64(Ah + (size_t)m0 * 1024);
    gb[1] = gmem_u64(Al + (size_t)m0 * 1024);
    gb[2] = gmem_u64(Bh + (size_t)n0 * 1024);
    gb[3] = gmem_u64(Bl + (size_t)n0 * 1024);

    const int lr = tid >> 3;
    const int lc = tid & 7;

    const int arow = warp_m + (lane & 15);
    const int a_chi = lane >> 4;
    const int ax = arow & 7;
    const uint32_t arow128 = (uint32_t)arow * 128;
    const int g = lane >> 3;
    const int brow = warp_n + ((g >> 1) << 3) + (lane & 7);
    const int b_chi = g & 1;
    const int bx = brow & 7;
    const uint32_t brow128 = (uint32_t)brow * 128;

    float acc[4][4][4];
#pragma unroll
    for (int mi = 0; mi < 4; mi++)
#pragma unroll
        for (int nj = 0; nj < 4; nj++)
#pragma unroll
            for (int r = 0; r < 4; r++) acc[mi][nj][r] = 0.f;

    auto issue_chunk = [&](int c) {
        const int k0 = c << 6;
        const uint32_t st = smb + (uint32_t)(c % 3) * STAGE_BYTES;
#pragma unroll
        for (int op = 0; op < 4; op++) {
#pragma unroll
            for (int rb = 0; rb < 4; rb++) {
                const int row = (rb << 5) + lr;
                const uint64_t ga = gb[op] + ((size_t)row * 1024 + k0 + (lc << 3)) * 2;
                const uint32_t sa = st + op * 16384 + swz((uint32_t)row * 128 + (lc << 4));
                cp16(sa, ga);
            }
        }
        CP_COMMIT();
    };

    issue_chunk(0);
    issue_chunk(1);

    for (int c = 0; c < 16; c++) {
        if (c < 15) { CP_WAIT(1); } else { CP_WAIT(0); }
        __syncthreads();
        if (c + 2 < 16) issue_chunk(c + 2);

        const uint32_t st = smb + (uint32_t)(c % 3) * STAGE_BYTES;

#pragma unroll
        for (int ks = 0; ks < 4; ks++) {
            uint32_t Ahf[4][4], Alf[4][4], Bhf[4][2], Blf[4][2];
            const uint32_t acol = (uint32_t)((((ks << 1) | a_chi) ^ ax) << 4);
            const uint32_t bcol = (uint32_t)((((ks << 1) | b_chi) ^ bx) << 4);
#pragma unroll
            for (int mi = 0; mi < 4; mi++) {
                const uint32_t ad = st + arow128 + mi * 2048 + acol;
                ldmx4(Ahf[mi], ad);
                ldmx4(Alf[mi], ad + 16384);
            }
#pragma unroll
            for (int njj = 0; njj < 2; njj++) {
                const uint32_t bd = st + 32768 + brow128 + njj * 2048 + bcol;
                uint32_t t[4];
                ldmx4(t, bd);
                Bhf[njj*2][0] = t[0]; Bhf[njj*2][1] = t[1];
                Bhf[njj*2+1][0] = t[2]; Bhf[njj*2+1][1] = t[3];
                ldmx4(t, bd + 16384);
                Blf[njj*2][0] = t[0]; Blf[njj*2][1] = t[1];
                Blf[njj*2+1][0] = t[2]; Blf[njj*2+1][1] = t[3];
            }
#pragma unroll
            for (int mi = 0; mi < 4; mi++)
#pragma unroll
                for (int nj = 0; nj < 4; nj++) {
                    mma16816(acc[mi][nj], Ahf[mi], Bhf[nj]);
                    mma16816(acc[mi][nj], Ahf[mi], Blf[nj]);
                    mma16816(acc[mi][nj], Alf[mi], Bhf[nj]);
                }
        }
    }
    __syncthreads();

    float* eps = (float*)sm;
    const int eg = lane >> 2;
    const int eco = (lane & 3) << 1;
#pragma unroll
    for (int mi = 0; mi < 4; mi++)
#pragma unroll
        for (int nj = 0; nj < 4; nj++) {
            const int row0 = warp_m + (mi << 4) + eg;
            const int col  = warp_n + (nj << 3) + eco;
            *(float2*)&eps[row0 * 136 + col] = make_float2(acc[mi][nj][0], acc[mi][nj][1]);
            *(float2*)&eps[(row0 + 8) * 136 + col] = make_float2(acc[mi][nj][2], acc[mi][nj][3]);
        }
    __syncthreads();

#pragma unroll
    for (int i = 0; i < 16; i++) {
        const int idx = tid + (i << 8);
        const int row = idx >> 5;
        const int c4  = idx & 31;
        const int n   = n0 + (c4 << 2);
        const int m   = m0 + row;
        float4 v = *(const float4*)&eps[row * 136 + (c4 << 2)];
        if (MODE == 2) {
            const float bb = bias[m];
            v.x += bb; v.y += bb; v.z += bb; v.w += bb;
        } else {
            const float4 bb = *(const float4*)&bias[n];
            v.x += bb.x; v.y += bb.y; v.z += bb.z; v.w += bb.w;
        }
        if (MODE == 0) {
            *(float4*)&C[(size_t)m * 1024 + n] = v;
        } else if (MODE == 1) {
            __half* Dq = (__half*)Dh_;
            v.x *= oscale; v.y *= oscale; v.z *= oscale; v.w *= oscale;
            const int bq_ = m >> 11, s = m & 2047, h0 = n >> 6, d = n & 63;
            const size_t base = (((size_t)(bq_ * HH + h0)) * SS + s) * DK + d;
            *(uint2*)&Dq[base] = make_uint2(pack_f16(v.x, v.y), pack_f16(v.z, v.w));
        } else {
            __half* Dh = (__half*)Dh_;
            __half* Dl = (__half*)Dl_;
            const int h0 = m >> 6, d = m & 63, bq_ = n >> 11, s = n & 2047;
            const size_t base = (((size_t)(bq_ * HH + h0)) * DK + d) * SS + s;
            uint32_t h01, l01, h23, l23;
            pack_hilo_f16(v.x, v.y, h01, l01);
            pack_hilo_f16(v.z, v.w, h23, l23);
            *(uint2*)&Dh[base] = make_uint2(h01, h23);
            *(uint2*)&Dl[base] = make_uint2(l01, l23);
        }
    }
}

// Merged Q/K/V projection: 768 blocks. [0,256)=Q, [256,512)=K, [512,768)=V^T
__global__ void __launch_bounds__(256, 1)
proj_kernel(const float* __restrict__ bq, const float* __restrict__ bk,
            const float* __restrict__ bv)
{
    const int bid = blockIdx.x;
    if (bid < 512) {
        const int z = bid >> 8;
        const int t = bid & 255;
        const int m0 = (t >> 3) << 7;
        const int n0 = (t & 7) << 7;
        const __nv_bfloat16* Ah = g_act_hi + (size_t)z * ACT_N;
        const __nv_bfloat16* Al = g_act_lo + (size_t)z * ACT_N;
        const __nv_bfloat16* Bh = g_w_hi + (size_t)z * W_N;
        const __nv_bfloat16* Bl = g_w_lo + (size_t)z * W_N;
        if (z == 0)
            gemm_tc<1>(m0, n0, Ah, Al, Bh, Bl, bq, nullptr, g_q16, nullptr,
                       0.125f * 1.4426950408889634f);
        else
            gemm_tc<1>(m0, n0, Ah, Al, Bh, Bl, bk, nullptr, g_k16, nullptr, 1.0f);
    } else {
        const int t = bid - 512;
        const int m0 = (t >> 5) << 7;
        const int n0 = (t & 31) << 7;
        gemm_tc<2>(m0, n0, g_w_hi + 2 * W_N, g_w_lo + 2 * W_N,
                   g_act_hi + 2 * ACT_N, g_act_lo + 2 * ACT_N,
                   bv, nullptr, g_vt_hi, g_vt_lo, 1.0f);
    }
}

__global__ void __launch_bounds__(256, 1)
out_tc_kernel(const float* __restrict__ bo, float* __restrict__ out)
{
    const int m0 = blockIdx.y << 7;
    const int n0 = blockIdx.x << 7;
    gemm_tc<0>(m0, n0, g_attn_hi, g_attn_lo, g_w_hi + 3 * W_N, g_w_lo + 3 * W_N,
               bo, out, nullptr, nullptr, 1.0f);
}

// ---------------------------------------------------------------------------
// Flash attention, fp16 single-pass QK + 2-pass fp16 PV. 2 CTAs/SM.
// CTA = 256 threads, 128 q-rows. smem: [0,16K) Q fp16, [16K,88K) 3-stage
// ring (K|Vhi|Vlo, 8KB each = 24KB/stage). Single sync per tile
// (issue(t+2) overwrites stage (t-1)%3 whose reads finished pre-sync).
// Mask: packed bits. Softmax: log2 domain, ex2, lane-partial l.
// ---------------------------------------------------------------------------
#define FLASH_STAGE 24576
#define FLASH_SMEM (16384 + 3 * FLASH_STAGE)   // 88 KB

__global__ void __launch_bounds__(256, 2)
flash_mma_kernel(const int* __restrict__ mask)
{
    extern __shared__ char sm[];
    const uint32_t smb = smem_u32(sm);
    const uint32_t ring = smb + 16384;
    const int tid  = threadIdx.x;
    const int wid  = tid >> 5;
    const int lane = tid & 31;
    const int b = blockIdx.z, h = blockIdx.y;
    const int bh = b * HH + h;
    const int q0 = blockIdx.x << 7;

    const int lr = tid >> 3;
    const int lc = tid & 7;

    // ---- stage Q (fp16 single) into [0,16K)
    {
        const uint64_t gq = gmem_u64(g_q16 + ((size_t)bh * SS + q0) * DK);
#pragma unroll
        for (int rs = 0; rs < 4; rs++) {
            const int row = (rs << 5) + lr;
            cp16(smb + swz((uint32_t)row * 128 + (lc << 4)),
                 gq + ((size_t)row * 64 + (lc << 3)) * 2);
        }
        CP_COMMIT(); CP_WAIT(0);
        __syncthreads();
    }

    // Q A-fragments (fp16)
    const int arowA = (wid << 4) + (lane & 15);
    const int a_chi = lane >> 4;
    const int axA = arowA & 7;
    const uint32_t arowA128 = (uint32_t)arowA * 128;

    uint32_t qh[4][4];
#pragma unroll
    for (int ks = 0; ks < 4; ks++) {
        const uint32_t col = (uint32_t)((((ks << 1) | a_chi) ^ axA) << 4);
        ldmx4(qh[ks], smb + arowA128 + col);
    }

    const uint64_t gk  = gmem_u64(g_k16 + (size_t)bh * SS * DK);
    const uint64_t gvh = gmem_u64(g_vt_hi + (size_t)bh * DK * SS);
    const uint64_t gvl = gmem_u64(g_vt_lo + (size_t)bh * DK * SS);

    auto issue = [&](int t) {
        const uint32_t st = ring + (uint32_t)(t % 3) * FLASH_STAGE;
        const int kv0 = t << 6;
#pragma unroll
        for (int rs = 0; rs < 2; rs++) {
            const int row = (rs << 5) + lr;
            const uint32_t so = swz((uint32_t)row * 128 + (lc << 4));
            const uint64_t voff = ((size_t)row * SS + kv0 + (lc << 3)) * 2;
            cp16(st + so,         gk + (((size_t)(kv0 + row)) * 64 + (lc << 3)) * 2);
            cp16(st + 8192 + so,  gvh + voff);
            cp16(st + 16384 + so, gvl + voff);
        }
        CP_COMMIT();
    };

    issue(0);
    issue(1);

    // B-fragment addressing for K / V^T
    const int gq_ = lane >> 3;
    const int brl = ((gq_ >> 1) << 3) | (lane & 7);
    const int bchi = gq_ & 1;
    const int bxr = brl & 7;

    const int qrow = q0 + (wid << 4) + (lane >> 2);
    const ull* mb0 = g_maskbits + (size_t)qrow * 32;
    const ull* mb1 = mb0 + 8 * 32;
    const int cbase = (lane & 3) << 1;

    float o[8][4];
#pragma unroll
    for (int nj = 0; nj < 8; nj++)
#pragma unroll
        for (int r = 0; r < 4; r++) o[nj][r] = 0.f;
    float m0 = -3e38f, m1 = -3e38f, l0 = 0.f, l1 = 0.f;   // l lane-partial

    for (int t = 0; t < 32; t++) {
        if (t < 31) { CP_WAIT(1); } else { CP_WAIT(0); }
        __syncthreads();
        if (t + 2 < 32) issue(t + 2);

        const uint32_t st = ring + (uint32_t)(t % 3) * FLASH_STAGE;

        // mask bits for this tile
        const ull w0 = mb0[t];
        const ull w1 = mb1[t];

        // ---- S = Q K^T (single-pass fp16)
        float sc[8][4];
#pragma unroll
        for (int nj = 0; nj < 8; nj++)
#pragma unroll
            for (int r = 0; r < 4; r++) sc[nj][r] = 0.f;

#pragma unroll
        for (int ks = 0; ks < 4; ks++) {
            const uint32_t col = (uint32_t)((((ks << 1) | bchi) ^ bxr) << 4);
#pragma unroll
            for (int njj = 0; njj < 4; njj++) {
                uint32_t tK[4];
                ldmx4(tK, st + (uint32_t)((njj << 4) + brl) * 128 + col);
                mma16816f16(sc[2*njj],   qh[ks], tK);
                mma16816f16(sc[2*njj+1], qh[ks], tK + 2);
            }
        }

        // ---- mask (bit tests) + online softmax (log2 domain)
        float mx0 = -3e38f, mx1 = -3e38f;
#pragma unroll
        for (int nj = 0; nj < 8; nj++) {
            const int sh = (nj << 3) + cbase;
            const uint32_t b0 = (uint32_t)(w0 >> sh);
            const uint32_t b1 = (uint32_t)(w1 >> sh);
            sc[nj][0] = (b0 & 1) ? sc[nj][0] : -1e9f;
            sc[nj][1] = (b0 & 2) ? sc[nj][1] : -1e9f;
            sc[nj][2] = (b1 & 1) ? sc[nj][2] : -1e9f;
            sc[nj][3] = (b1 & 2) ? sc[nj][3] : -1e9f;
            mx0 = fmaxf(mx0, fmaxf(sc[nj][0], sc[nj][1]));
            mx1 = fmaxf(mx1, fmaxf(sc[nj][2], sc[nj][3]));
        }
        mx0 = fmaxf(mx0, __shfl_xor_sync(0xffffffffu, mx0, 1));
        mx0 = fmaxf(mx0, __shfl_xor_sync(0xffffffffu, mx0, 2));
        mx1 = fmaxf(mx1, __shfl_xor_sync(0xffffffffu, mx1, 1));
        mx1 = fmaxf(mx1, __shfl_xor_sync(0xffffffffu, mx1, 2));

        const float mn0 = fmaxf(m0, mx0);
        const float mn1 = fmaxf(m1, mx1);
        const float a0 = ex2f(m0 - mn0);
        const float a1 = ex2f(m1 - mn1);
        m0 = mn0; m1 = mn1;

        float s0 = 0.f, s1 = 0.f;
#pragma unroll
        for (int nj = 0; nj < 8; nj++) {
            sc[nj][0] = ex2f(sc[nj][0] - mn0);
            sc[nj][1] = ex2f(sc[nj][1] - mn0);
            sc[nj][2] = ex2f(sc[nj][2] - mn1);
            sc[nj][3] = ex2f(sc[nj][3] - mn1);
            s0 += sc[nj][0] + sc[nj][1];
            s1 += sc[nj][2] + sc[nj][3];
        }
        l0 = l0 * a0 + s0;
        l1 = l1 * a1 + s1;

        // O *= alpha before in-tile PV
#pragma unroll
        for (int nj = 0; nj < 8; nj++) {
            o[nj][0] *= a0; o[nj][1] *= a0;
            o[nj][2] *= a1; o[nj][3] *= a1;
        }

        // ---- O += P V (in-tile; P fp16, V^T fp16 hi/lo 2-pass)
#pragma unroll
        for (int kt = 0; kt < 4; kt++) {
            uint32_t pkk[4];
            pkk[0] = pack_f16(sc[2*kt][0],   sc[2*kt][1]);
            pkk[1] = pack_f16(sc[2*kt][2],   sc[2*kt][3]);
            pkk[2] = pack_f16(sc[2*kt+1][0], sc[2*kt+1][1]);
            pkk[3] = pack_f16(sc[2*kt+1][2], sc[2*kt+1][3]);
            const uint32_t col = (uint32_t)((((kt << 1) | bchi) ^ bxr) << 4);
#pragma unroll
            for (int njj = 0; njj < 4; njj++) {
                const uint32_t rb = st + 8192 + (uint32_t)((njj << 4) + brl) * 128 + col;
                uint32_t vH[4], vL[4];
                ldmx4(vH, rb);
                ldmx4(vL, rb + 8192);
                mma16816f16(o[2*njj],   pkk, vH);
                mma16816f16(o[2*njj],   pkk, vL);
                mma16816f16(o[2*njj+1], pkk, vH + 2);
                mma16816f16(o[2*njj+1], pkk, vL + 2);
            }
        }
    }

    // ---- epilogue: quad-reduce l, normalize, split hi/lo
    l0 += __shfl_xor_sync(0xffffffffu, l0, 1);
    l0 += __shfl_xor_sync(0xffffffffu, l0, 2);
    l1 += __shfl_xor_sync(0xffffffffu, l1, 1);
    l1 += __shfl_xor_sync(0xffffffffu, l1, 2);
    const float i0 = 1.0f / l0;
    const float i1 = 1.0f / l1;
    const size_t ro0 = ((size_t)(b * SS + q0 + (wid << 4) + (lane >> 2))) * DM + h * DK;
    const size_t ro1 = ro0 + (size_t)8 * DM;
#pragma unroll
    for (int nj = 0; nj < 8; nj++) {
        const int colg = (nj << 3) + cbase;
        uint32_t hi, lo;
        pack_hilo(o[nj][0] * i0, o[nj][1] * i0, hi, lo);
        *(uint32_t*)&g_attn_hi[ro0 + colg] = hi;
        *(uint32_t*)&g_attn_lo[ro0 + colg] = lo;
        pack_hilo(o[nj][2] * i1, o[nj][3] * i1, hi, lo);
        *(uint32_t*)&g_attn_hi[ro1 + colg] = hi;
        *(uint32_t*)&g_attn_lo[ro1 + colg] = lo;
    }
}

// ---------------------------------------------------------------------------
extern "C" void kernel_launch(void* const* d_in, const int* in_sizes, int n_in,
                              void* d_out, int out_size)
{
    const float* q    = (const float*)d_in[0];
    const float* k    = (const float*)d_in[1];
    const float* v    = (const float*)d_in[2];
    const int*   mask = (const int*)  d_in[3];
    const float* wq   = (const float*)d_in[4];
    const float* bq   = (const float*)d_in[5];
    const float* wk   = (const float*)d_in[6];
    const float* bk   = (const float*)d_in[7];
    const float* wv   = (const float*)d_in[8];
    const float* bv   = (const float*)d_in[9];
    const float* wo   = (const float*)d_in[10];
    const float* bo   = (const float*)d_in[11];
    float* out = (float*)d_out;

    cudaFuncSetAttribute(proj_kernel, cudaFuncAttributeMaxDynamicSharedMemorySize, TC_SMEM);
    cudaFuncSetAttribute(out_tc_kernel, cudaFuncAttributeMaxDynamicSharedMemorySize, TC_SMEM);
    cudaFuncSetAttribute(flash_mma_kernel, cudaFuncAttributeMaxDynamicSharedMemorySize, FLASH_SMEM);

    split_kernel<<<dim3(4096, 1, 7), 256>>>(q, k, v, wq, wk, wv, wo);
    mask_pack_kernel<<<256, 256>>>(mask);
    proj_kernel<<<768, 256, TC_SMEM>>>(bq, bk, bv);
    flash_mma_kernel<<<dim3(16, 16, 2), 256, FLASH_SMEM>>>(mask);
    out_tc_kernel<<<dim3(8, 32, 1), 256, TC_SMEM>>>(bo, out);
}

// round 16
// speedup vs baseline: 1.6298x; 1.1827x over previous
#include <cuda_runtime.h>
#include <cuda_bf16.h>
#include <cuda_fp16.h>
#include <cstdint>

#define BB 2
#define SS 2048
#define DM 1024
#define HH 16
#define DK 64

typedef unsigned long long ull;

#define ACT_N ((size_t)4096 * 1024)
#define W_N   ((size_t)1024 * 1024)

// Scratch (__device__ globals; allocation-free rule)
__device__ __align__(16) __half g_act16[2 * ACT_N];           // q,k inputs fp16
__device__ __align__(16) __half g_w16[2 * W_N];               // wq,wk fp16
__device__ __align__(16) __nv_bfloat16 g_actv_hi[ACT_N];      // v input split
__device__ __align__(16) __nv_bfloat16 g_actv_lo[ACT_N];
__device__ __align__(16) __nv_bfloat16 g_w_hi[2 * W_N];       // wv,wo split
__device__ __align__(16) __nv_bfloat16 g_w_lo[2 * W_N];
__device__ __align__(16) __half g_q16[BB*HH*SS*DK];           // [BH][S][64] fp16 (x0.125*log2e)
__device__ __align__(16) __half g_k16[BB*HH*SS*DK];           // [BH][S][64] fp16
__device__ __align__(16) __half g_vt_hi[BB*HH*SS*DK];         // [BH][64][S] V^T fp16 hi
__device__ __align__(16) __half g_vt_lo[BB*HH*SS*DK];         // fp16 residual
__device__ __align__(16) __nv_bfloat16 g_attn_hi[ACT_N];      // flash out split
__device__ __align__(16) __nv_bfloat16 g_attn_lo[ACT_N];
__device__ ull g_maskbits[SS * (SS / 64)];                    // 512 KB bit mask

// ---------------- helpers ----------------
__device__ __forceinline__ uint32_t smem_u32(const void* p) {
    uint32_t a;
    asm("{ .reg .u64 t; cvta.to.shared.u64 t, %1; cvt.u32.u64 %0, t; }"
        : "=r"(a) : "l"(p));
    return a;
}
__device__ __forceinline__ uint64_t gmem_u64(const void* p) {
    uint64_t a;
    asm("cvta.to.global.u64 %0, %1;" : "=l"(a) : "l"(p));
    return a;
}
__device__ __forceinline__ void mma16816(float* c, const uint32_t* a, const uint32_t* b) {
    asm volatile(
        "mma.sync.aligned.m16n8k16.row.col.f32.bf16.bf16.f32 "
        "{%0,%1,%2,%3}, {%4,%5,%6,%7}, {%8,%9}, {%0,%1,%2,%3};"
        : "+f"(c[0]), "+f"(c[1]), "+f"(c[2]), "+f"(c[3])
        : "r"(a[0]), "r"(a[1]), "r"(a[2]), "r"(a[3]), "r"(b[0]), "r"(b[1]));
}
__device__ __forceinline__ void mma16816f16(float* c, const uint32_t* a, const uint32_t* b) {
    asm volatile(
        "mma.sync.aligned.m16n8k16.row.col.f32.f16.f16.f32 "
        "{%0,%1,%2,%3}, {%4,%5,%6,%7}, {%8,%9}, {%0,%1,%2,%3};"
        : "+f"(c[0]), "+f"(c[1]), "+f"(c[2]), "+f"(c[3])
        : "r"(a[0]), "r"(a[1]), "r"(a[2]), "r"(a[3]), "r"(b[0]), "r"(b[1]));
}
__device__ __forceinline__ void ldmx4(uint32_t* r, uint32_t addr) {
    asm volatile("ldmatrix.sync.aligned.m8n8.x4.shared.b16 {%0,%1,%2,%3}, [%4];"
                 : "=r"(r[0]), "=r"(r[1]), "=r"(r[2]), "=r"(r[3]) : "r"(addr));
}
__device__ __forceinline__ void cp16(uint32_t saddr, uint64_t gaddr) {
    asm volatile("cp.async.cg.shared.global [%0], [%1], 16;"
                 :: "r"(saddr), "l"(gaddr) : "memory");
}
#define CP_COMMIT() asm volatile("cp.async.commit_group;" ::: "memory")
#define CP_WAIT(n)  asm volatile("cp.async.wait_group %0;" :: "n"(n) : "memory")

__device__ __forceinline__ uint32_t swz(uint32_t x) { return x ^ ((x >> 3) & 0x70); }

__device__ __forceinline__ float ex2f(float x) {
    float y; asm("ex2.approx.f32 %0, %1;" : "=f"(y) : "f"(x)); return y;
}

// pack two fp32 -> bf16x2 hi + bf16x2 residual lo
__device__ __forceinline__ void pack_hilo(float x0, float x1, uint32_t& hi, uint32_t& lo) {
    uint32_t h;
    asm("cvt.rn.bf16x2.f32 %0, %1, %2;" : "=r"(h) : "f"(x1), "f"(x0));
    const float h0 = __uint_as_float(h << 16);
    const float h1 = __uint_as_float(h & 0xffff0000u);
    uint32_t l;
    asm("cvt.rn.bf16x2.f32 %0, %1, %2;" : "=r"(l) : "f"(x1 - h1), "f"(x0 - h0));
    hi = h; lo = l;
}

// pack two fp32 -> f16x2 hi + f16x2 residual lo
__device__ __forceinline__ void pack_hilo_f16(float x0, float x1, uint32_t& hi, uint32_t& lo) {
    uint32_t h;
    asm("cvt.rn.f16x2.f32 %0, %1, %2;" : "=r"(h) : "f"(x1), "f"(x0));
    float h0, h1;
    asm("{ .reg .f16 a,b;\n\t mov.b32 {a,b}, %2;\n\t cvt.f32.f16 %0, a;\n\t cvt.f32.f16 %1, b; }"
        : "=f"(h0), "=f"(h1) : "r"(h));
    uint32_t l;
    asm("cvt.rn.f16x2.f32 %0, %1, %2;" : "=r"(l) : "f"(x1 - h1), "f"(x0 - h0));
    hi = h; lo = l;
}

// pack two fp32 -> single f16x2
__device__ __forceinline__ uint32_t pack_f16(float x0, float x1) {
    uint32_t r;
    asm("cvt.rn.f16x2.f32 %0, %1, %2;" : "=r"(r) : "f"(x1), "f"(x0));
    return r;
}

// ---------------------------------------------------------------------------
// Mask -> bit pack
// ---------------------------------------------------------------------------
__global__ void __launch_bounds__(256)
mask_pack_kernel(const int* __restrict__ mask)
{
    const int w = blockIdx.x * 256 + threadIdx.x;
    const int r = w >> 5, cw = w & 31;
    const int4* src = (const int4*)(mask + (size_t)r * SS + (cw << 6));
    ull bits = 0;
#pragma unroll
    for (int i = 0; i < 16; i++) {
        const int4 v = src[i];
        bits |= (ull)(v.x != 0) << (i * 4);
        bits |= (ull)(v.y != 0) << (i * 4 + 1);
        bits |= (ull)(v.z != 0) << (i * 4 + 2);
        bits |= (ull)(v.w != 0) << (i * 4 + 3);
    }
    g_maskbits[w] = bits;
}

// ---------------------------------------------------------------------------
// Split kernel. z=0,1: q,k -> fp16 single. z=2: v -> bf16 hi/lo.
// z=3,4: wq,wk -> fp16 single. z=5,6: wv,wo -> bf16 hi/lo.
// ---------------------------------------------------------------------------
__global__ void __launch_bounds__(256)
split_kernel(const float* __restrict__ q, const float* __restrict__ k,
             const float* __restrict__ v,
             const float* __restrict__ wq, const float* __restrict__ wk,
             const float* __restrict__ wv, const float* __restrict__ wo)
{
    const int z = blockIdx.z;
    const size_t i4 = (size_t)blockIdx.x * 256 + threadIdx.x;

    if (z == 0 || z == 1 || z == 3 || z == 4) {
        const float* src;
        __half* d16;
        size_t cnt;
        if (z == 0)      { src = q;  d16 = g_act16;          cnt = ACT_N; }
        else if (z == 1) { src = k;  d16 = g_act16 + ACT_N;  cnt = ACT_N; }
        else if (z == 3) { src = wq; d16 = g_w16;            cnt = W_N; }
        else             { src = wk; d16 = g_w16 + W_N;      cnt = W_N; }
        if (i4 * 4 >= cnt) return;
        float4 x = ((const float4*)src)[i4];
        *(uint2*)&d16[i4 * 4] = make_uint2(pack_f16(x.x, x.y), pack_f16(x.z, x.w));
    } else {
        const float* src;
        __nv_bfloat16 *dh, *dl;
        size_t cnt;
        if (z == 2)      { src = v;  dh = g_actv_hi;      dl = g_actv_lo;      cnt = ACT_N; }
        else if (z == 5) { src = wv; dh = g_w_hi;         dl = g_w_lo;         cnt = W_N; }
        else             { src = wo; dh = g_w_hi + W_N;   dl = g_w_lo + W_N;   cnt = W_N; }
        if (i4 * 4 >= cnt) return;
        float4 x = ((const float4*)src)[i4];
        uint32_t h01, l01, h23, l23;
        pack_hilo(x.x, x.y, h01, l01);
        pack_hilo(x.z, x.w, h23, l23);
        *(uint2*)&dh[i4 * 4] = make_uint2(h01, h23);
        *(uint2*)&dl[i4 * 4] = make_uint2(l01, l23);
    }
}

// ---------------------------------------------------------------------------
// 3-pass split-bf16 GEMM (control; V^T and out_proj).
// MODE 0: fp32 out. MODE 2: V^T -> fp16 hi/lo [BH][64][S].
// ---------------------------------------------------------------------------
#define STAGE_BYTES 65536
#define TC_SMEM (3 * STAGE_BYTES)

template <int MODE>
__device__ __forceinline__ void gemm_tc(int m0, int n0,
                                        const __nv_bfloat16* __restrict__ Ah,
                                        const __nv_bfloat16* __restrict__ Al,
                                        const __nv_bfloat16* __restrict__ Bh,
                                        const __nv_bfloat16* __restrict__ Bl,
                                        const float* __restrict__ bias,
                                        float* __restrict__ C,
                                        void* __restrict__ Dh_,
                                        void* __restrict__ Dl_)
{
    extern __shared__ char sm[];
    const uint32_t smb = smem_u32(sm);
    const int tid  = threadIdx.x;
    const int wid  = tid >> 5;
    const int lane = tid & 31;

    const int warp_m = (wid >> 2) << 6;
    const int warp_n = (wid & 3) << 5;

    uint64_t gb[4];
    gb[0] = gmem_u64(Ah + (size_t)m0 * 1024);
    gb[1] = gmem_u64(Al + (size_t)m0 * 1024);
    gb[2] = gmem_u64(Bh + (size_t)n0 * 1024);
    gb[3] = gmem_u64(Bl + (size_t)n0 * 1024);

    const int lr = tid >> 3;
    const int lc = tid & 7;

    const int arow = warp_m + (lane & 15);
    const int a_chi = lane >> 4;
    const int ax = arow & 7;
    const uint32_t arow128 = (uint32_t)arow * 128;
    const int g = lane >> 3;
    const int brow = warp_n + ((g >> 1) << 3) + (lane & 7);
    const int b_chi = g & 1;
    const int bx = brow & 7;
    const uint32_t brow128 = (uint32_t)brow * 128;

    float acc[4][4][4];
#pragma unroll
    for (int mi = 0; mi < 4; mi++)
#pragma unroll
        for (int nj = 0; nj < 4; nj++)
#pragma unroll
            for (int r = 0; r < 4; r++) acc[mi][nj][r] = 0.f;

    auto issue_chunk = [&](int c) {
        const int k0 = c << 6;
        const uint32_t st = smb + (uint32_t)(c % 3) * STAGE_BYTES;
#pragma unroll
        for (int op = 0; op < 4; op++) {
#pragma unroll
            for (int rb = 0; rb < 4; rb++) {
                const int row = (rb << 5) + lr;
                const uint64_t ga = gb[op] + ((size_t)row * 1024 + k0 + (lc << 3)) * 2;
                const uint32_t sa = st + op * 16384 + swz((uint32_t)row * 128 + (lc << 4));
                cp16(sa, ga);
            }
        }
        CP_COMMIT();
    };

    issue_chunk(0);
    issue_chunk(1);

    for (int c = 0; c < 16; c++) {
        if (c < 15) { CP_WAIT(1); } else { CP_WAIT(0); }
        __syncthreads();
        if (c + 2 < 16) issue_chunk(c + 2);

        const uint32_t st = smb + (uint32_t)(c % 3) * STAGE_BYTES;

#pragma unroll
        for (int ks = 0; ks < 4; ks++) {
            uint32_t Ahf[4][4], Alf[4][4], Bhf[4][2], Blf[4][2];
            const uint32_t acol = (uint32_t)((((ks << 1) | a_chi) ^ ax) << 4);
            const uint32_t bcol = (uint32_t)((((ks << 1) | b_chi) ^ bx) << 4);
#pragma unroll
            for (int mi = 0; mi < 4; mi++) {
                const uint32_t ad = st + arow128 + mi * 2048 + acol;
                ldmx4(Ahf[mi], ad);
                ldmx4(Alf[mi], ad + 16384);
            }
#pragma unroll
            for (int njj = 0; njj < 2; njj++) {
                const uint32_t bd = st + 32768 + brow128 + njj * 2048 + bcol;
                uint32_t t[4];
                ldmx4(t, bd);
                Bhf[njj*2][0] = t[0]; Bhf[njj*2][1] = t[1];
                Bhf[njj*2+1][0] = t[2]; Bhf[njj*2+1][1] = t[3];
                ldmx4(t, bd + 16384);
                Blf[njj*2][0] = t[0]; Blf[njj*2][1] = t[1];
                Blf[njj*2+1][0] = t[2]; Blf[njj*2+1][1] = t[3];
            }
#pragma unroll
            for (int mi = 0; mi < 4; mi++)
#pragma unroll
                for (int nj = 0; nj < 4; nj++) {
                    mma16816(acc[mi][nj], Ahf[mi], Bhf[nj]);
                    mma16816(acc[mi][nj], Ahf[mi], Blf[nj]);
                    mma16816(acc[mi][nj], Alf[mi], Bhf[nj]);
                }
        }
    }
    __syncthreads();

    float* eps = (float*)sm;
    const int eg = lane >> 2;
    const int eco = (lane & 3) << 1;
#pragma unroll
    for (int mi = 0; mi < 4; mi++)
#pragma unroll
        for (int nj = 0; nj < 4; nj++) {
            const int row0 = warp_m + (mi << 4) + eg;
            const int col  = warp_n + (nj << 3) + eco;
            *(float2*)&eps[row0 * 136 + col] = make_float2(acc[mi][nj][0], acc[mi][nj][1]);
            *(float2*)&eps[(row0 + 8) * 136 + col] = make_float2(acc[mi][nj][2], acc[mi][nj][3]);
        }
    __syncthreads();

#pragma unroll
    for (int i = 0; i < 16; i++) {
        const int idx = tid + (i << 8);
        const int row = idx >> 5;
        const int c4  = idx & 31;
        const int n   = n0 + (c4 << 2);
        const int m   = m0 + row;
        float4 v = *(const float4*)&eps[row * 136 + (c4 << 2)];
        if (MODE == 2) {
            const float bb = bias[m];
            v.x += bb; v.y += bb; v.z += bb; v.w += bb;
        } else {
            const float4 bb = *(const float4*)&bias[n];
            v.x += bb.x; v.y += bb.y; v.z += bb.z; v.w += bb.w;
        }
        if (MODE == 0) {
            *(float4*)&C[(size_t)m * 1024 + n] = v;
        } else {
            __half* Dh = (__half*)Dh_;
            __half* Dl = (__half*)Dl_;
            const int h0 = m >> 6, d = m & 63, bq_ = n >> 11, s = n & 2047;
            const size_t base = (((size_t)(bq_ * HH + h0)) * DK + d) * SS + s;
            uint32_t h01, l01, h23, l23;
            pack_hilo_f16(v.x, v.y, h01, l01);
            pack_hilo_f16(v.z, v.w, h23, l23);
            *(uint2*)&Dh[base] = make_uint2(h01, h23);
            *(uint2*)&Dl[base] = make_uint2(l01, l23);
        }
    }
}

// ---------------------------------------------------------------------------
// Single-pass fp16 GEMM for Q/K projections. A[M,K] fp16, B[N,K] fp16,
// fp32 accum; out fp16 split-head with scale. 3-stage pipeline, 32KB/stage.
// ---------------------------------------------------------------------------
#define STAGE16 32768

__device__ __forceinline__ void gemm16(int m0, int n0,
                                       const __half* __restrict__ A,
                                       const __half* __restrict__ B,
                                       const float* __restrict__ bias,
                                       __half* __restrict__ Dq, float oscale)
{
    extern __shared__ char sm[];
    const uint32_t smb = smem_u32(sm);
    const int tid  = threadIdx.x;
    const int wid  = tid >> 5;
    const int lane = tid & 31;

    const int warp_m = (wid >> 2) << 6;
    const int warp_n = (wid & 3) << 5;

    const uint64_t gA = gmem_u64(A + (size_t)m0 * 1024);
    const uint64_t gB = gmem_u64(B + (size_t)n0 * 1024);

    const int lr = tid >> 3;
    const int lc = tid & 7;

    const int arow = warp_m + (lane & 15);
    const int a_chi = lane >> 4;
    const int ax = arow & 7;
    const uint32_t arow128 = (uint32_t)arow * 128;
    const int g = lane >> 3;
    const int brow = warp_n + ((g >> 1) << 3) + (lane & 7);
    const int b_chi = g & 1;
    const int bx = brow & 7;
    const uint32_t brow128 = (uint32_t)brow * 128;

    float acc[4][4][4];
#pragma unroll
    for (int mi = 0; mi < 4; mi++)
#pragma unroll
        for (int nj = 0; nj < 4; nj++)
#pragma unroll
            for (int r = 0; r < 4; r++) acc[mi][nj][r] = 0.f;

    auto issue_chunk = [&](int c) {
        const int k0 = c << 6;
        const uint32_t st = smb + (uint32_t)(c % 3) * STAGE16;
#pragma unroll
        for (int rb = 0; rb < 4; rb++) {
            const int row = (rb << 5) + lr;
            const uint32_t so = swz((uint32_t)row * 128 + (lc << 4));
            const uint64_t off = ((size_t)row * 1024 + k0 + (lc << 3)) * 2;
            cp16(st + so,         gA + off);
            cp16(st + 16384 + so, gB + off);
        }
        CP_COMMIT();
    };

    issue_chunk(0);
    issue_chunk(1);

    for (int c = 0; c < 16; c++) {
        if (c < 15) { CP_WAIT(1); } else { CP_WAIT(0); }
        __syncthreads();
        if (c + 2 < 16) issue_chunk(c + 2);

        const uint32_t st = smb + (uint32_t)(c % 3) * STAGE16;

#pragma unroll
        for (int ks = 0; ks < 4; ks++) {
            uint32_t Af[4][4], Bf[4][2];
            const uint32_t acol = (uint32_t)((((ks << 1) | a_chi) ^ ax) << 4);
            const uint32_t bcol = (uint32_t)((((ks << 1) | b_chi) ^ bx) << 4);
#pragma unroll
            for (int mi = 0; mi < 4; mi++)
                ldmx4(Af[mi], st + arow128 + mi * 2048 + acol);
#pragma unroll
            for (int njj = 0; njj < 2; njj++) {
                uint32_t t[4];
                ldmx4(t, st + 16384 + brow128 + njj * 2048 + bcol);
                Bf[njj*2][0] = t[0]; Bf[njj*2][1] = t[1];
                Bf[njj*2+1][0] = t[2]; Bf[njj*2+1][1] = t[3];
            }
#pragma unroll
            for (int mi = 0; mi < 4; mi++)
#pragma unroll
                for (int nj = 0; nj < 4; nj++)
                    mma16816f16(acc[mi][nj], Af[mi], Bf[nj]);
        }
    }
    __syncthreads();

    float* eps = (float*)sm;
    const int eg = lane >> 2;
    const int eco = (lane & 3) << 1;
#pragma unroll
    for (int mi = 0; mi < 4; mi++)
#pragma unroll
        for (int nj = 0; nj < 4; nj++) {
            const int row0 = warp_m + (mi << 4) + eg;
            const int col  = warp_n + (nj << 3) + eco;
            *(float2*)&eps[row0 * 136 + col] = make_float2(acc[mi][nj][0], acc[mi][nj][1]);
            *(float2*)&eps[(row0 + 8) * 136 + col] = make_float2(acc[mi][nj][2], acc[mi][nj][3]);
        }
    __syncthreads();

#pragma unroll
    for (int i = 0; i < 16; i++) {
        const int idx = tid + (i << 8);
        const int row = idx >> 5;
        const int c4  = idx & 31;
        const int n   = n0 + (c4 << 2);
        const int m   = m0 + row;
        float4 v = *(const float4*)&eps[row * 136 + (c4 << 2)];
        const float4 bb = *(const float4*)&bias[n];
        v.x = (v.x + bb.x) * oscale; v.y = (v.y + bb.y) * oscale;
        v.z = (v.z + bb.z) * oscale; v.w = (v.w + bb.w) * oscale;
        const int bq_ = m >> 11, s = m & 2047, h0 = n >> 6, d = n & 63;
        const size_t base = (((size_t)(bq_ * HH + h0)) * SS + s) * DK + d;
        *(uint2*)&Dq[base] = make_uint2(pack_f16(v.x, v.y), pack_f16(v.z, v.w));
    }
}

// Merged Q/K/V projection: 768 blocks. [0,256)=Q fp16, [256,512)=K fp16,
// [512,768)=V^T 3-pass bf16.
__global__ void __launch_bounds__(256, 1)
proj_kernel(const float* __restrict__ bq, const float* __restrict__ bk,
            const float* __restrict__ bv)
{
    const int bid = blockIdx.x;
    if (bid < 512) {
        const int z = bid >> 8;
        const int t = bid & 255;
        const int m0 = (t >> 3) << 7;
        const int n0 = (t & 7) << 7;
        if (z == 0)
            gemm16(m0, n0, g_act16, g_w16, bq, g_q16,
                   0.125f * 1.4426950408889634f);
        else
            gemm16(m0, n0, g_act16 + ACT_N, g_w16 + W_N, bk, g_k16, 1.0f);
    } else {
        const int t = bid - 512;
        const int m0 = (t >> 5) << 7;
        const int n0 = (t & 31) << 7;
        gemm_tc<2>(m0, n0, g_w_hi, g_w_lo, g_actv_hi, g_actv_lo,
                   bv, nullptr, g_vt_hi, g_vt_lo);
    }
}

__global__ void __launch_bounds__(256, 1)
out_tc_kernel(const float* __restrict__ bo, float* __restrict__ out)
{
    const int m0 = blockIdx.y << 7;
    const int n0 = blockIdx.x << 7;
    gemm_tc<0>(m0, n0, g_attn_hi, g_attn_lo, g_w_hi + W_N, g_w_lo + W_N,
               bo, out, nullptr, nullptr);
}

// ---------------------------------------------------------------------------
// Flash attention (r15, unchanged): fp16 single QK + 2-pass fp16 PV,
// 2 CTAs/SM, 3-stage ring, single sync/tile, bitmask, log2 softmax.
// ---------------------------------------------------------------------------
#define FLASH_STAGE 24576
#define FLASH_SMEM (16384 + 3 * FLASH_STAGE)   // 88 KB

__global__ void __launch_bounds__(256, 2)
flash_mma_kernel(const int* __restrict__ mask)
{
    extern __shared__ char sm[];
    const uint32_t smb = smem_u32(sm);
    const uint32_t ring = smb + 16384;
    const int tid  = threadIdx.x;
    const int wid  = tid >> 5;
    const int lane = tid & 31;
    const int b = blockIdx.z, h = blockIdx.y;
    const int bh = b * HH + h;
    const int q0 = blockIdx.x << 7;

    const int lr = tid >> 3;
    const int lc = tid & 7;

    // ---- stage Q (fp16) into [0,16K)
    {
        const uint64_t gq = gmem_u64(g_q16 + ((size_t)bh * SS + q0) * DK);
#pragma unroll
        for (int rs = 0; rs < 4; rs++) {
            const int row = (rs << 5) + lr;
            cp16(smb + swz((uint32_t)row * 128 + (lc << 4)),
                 gq + ((size_t)row * 64 + (lc << 3)) * 2);
        }
        CP_COMMIT(); CP_WAIT(0);
        __syncthreads();
    }

    const int arowA = (wid << 4) + (lane & 15);
    const int a_chi = lane >> 4;
    const int axA = arowA & 7;
    const uint32_t arowA128 = (uint32_t)arowA * 128;

    uint32_t qh[4][4];
#pragma unroll
    for (int ks = 0; ks < 4; ks++) {
        const uint32_t col = (uint32_t)((((ks << 1) | a_chi) ^ axA) << 4);
        ldmx4(qh[ks], smb + arowA128 + col);
    }

    const uint64_t gk  = gmem_u64(g_k16 + (size_t)bh * SS * DK);
    const uint64_t gvh = gmem_u64(g_vt_hi + (size_t)bh * DK * SS);
    const uint64_t gvl = gmem_u64(g_vt_lo + (size_t)bh * DK * SS);

    auto issue = [&](int t) {
        const uint32_t st = ring + (uint32_t)(t % 3) * FLASH_STAGE;
        const int kv0 = t << 6;
#pragma unroll
        for (int rs = 0; rs < 2; rs++) {
            const int row = (rs << 5) + lr;
            const uint32_t so = swz((uint32_t)row * 128 + (lc << 4));
            const uint64_t voff = ((size_t)row * SS + kv0 + (lc << 3)) * 2;
            cp16(st + so,         gk + (((size_t)(kv0 + row)) * 64 + (lc << 3)) * 2);
            cp16(st + 8192 + so,  gvh + voff);
            cp16(st + 16384 + so, gvl + voff);
        }
        CP_COMMIT();
    };

    issue(0);
    issue(1);

    const int gq_ = lane >> 3;
    const int brl = ((gq_ >> 1) << 3) | (lane & 7);
    const int bchi = gq_ & 1;
    const int bxr = brl & 7;

    const int qrow = q0 + (wid << 4) + (lane >> 2);
    const ull* mb0 = g_maskbits + (size_t)qrow * 32;
    const ull* mb1 = mb0 + 8 * 32;
    const int cbase = (lane & 3) << 1;

    float o[8][4];
#pragma unroll
    for (int nj = 0; nj < 8; nj++)
#pragma unroll
        for (int r = 0; r < 4; r++) o[nj][r] = 0.f;
    float m0 = -3e38f, m1 = -3e38f, l0 = 0.f, l1 = 0.f;

    for (int t = 0; t < 32; t++) {
        if (t < 31) { CP_WAIT(1); } else { CP_WAIT(0); }
        __syncthreads();
        if (t + 2 < 32) issue(t + 2);

        const uint32_t st = ring + (uint32_t)(t % 3) * FLASH_STAGE;

        const ull w0 = mb0[t];
        const ull w1 = mb1[t];

        // ---- S = Q K^T (single-pass fp16)
        float sc[8][4];
#pragma unroll
        for (int nj = 0; nj < 8; nj++)
#pragma unroll
            for (int r = 0; r < 4; r++) sc[nj][r] = 0.f;

#pragma unroll
        for (int ks = 0; ks < 4; ks++) {
            const uint32_t col = (uint32_t)((((ks << 1) | bchi) ^ bxr) << 4);
#pragma unroll
            for (int njj = 0; njj < 4; njj++) {
                uint32_t tK[4];
                ldmx4(tK, st + (uint32_t)((njj << 4) + brl) * 128 + col);
                mma16816f16(sc[2*njj],   qh[ks], tK);
                mma16816f16(sc[2*njj+1], qh[ks], tK + 2);
            }
        }

        // ---- mask + online softmax (log2 domain)
        float mx0 = -3e38f, mx1 = -3e38f;
#pragma unroll
        for (int nj = 0; nj < 8; nj++) {
            const int sh = (nj << 3) + cbase;
            const uint32_t b0 = (uint32_t)(w0 >> sh);
            const uint32_t b1 = (uint32_t)(w1 >> sh);
            sc[nj][0] = (b0 & 1) ? sc[nj][0] : -1e9f;
            sc[nj][1] = (b0 & 2) ? sc[nj][1] : -1e9f;
            sc[nj][2] = (b1 & 1) ? sc[nj][2] : -1e9f;
            sc[nj][3] = (b1 & 2) ? sc[nj][3] : -1e9f;
            mx0 = fmaxf(mx0, fmaxf(sc[nj][0], sc[nj][1]));
            mx1 = fmaxf(mx1, fmaxf(sc[nj][2], sc[nj][3]));
        }
        mx0 = fmaxf(mx0, __shfl_xor_sync(0xffffffffu, mx0, 1));
        mx0 = fmaxf(mx0, __shfl_xor_sync(0xffffffffu, mx0, 2));
        mx1 = fmaxf(mx1, __shfl_xor_sync(0xffffffffu, mx1, 1));
        mx1 = fmaxf(mx1, __shfl_xor_sync(0xffffffffu, mx1, 2));

        const float mn0 = fmaxf(m0, mx0);
        const float mn1 = fmaxf(m1, mx1);
        const float a0 = ex2f(m0 - mn0);
        const float a1 = ex2f(m1 - mn1);
        m0 = mn0; m1 = mn1;

        float s0 = 0.f, s1 = 0.f;
#pragma unroll
        for (int nj = 0; nj < 8; nj++) {
            sc[nj][0] = ex2f(sc[nj][0] - mn0);
            sc[nj][1] = ex2f(sc[nj][1] - mn0);
            sc[nj][2] = ex2f(sc[nj][2] - mn1);
            sc[nj][3] = ex2f(sc[nj][3] - mn1);
            s0 += sc[nj][0] + sc[nj][1];
            s1 += sc[nj][2] + sc[nj][3];
        }
        l0 = l0 * a0 + s0;
        l1 = l1 * a1 + s1;

#pragma unroll
        for (int nj = 0; nj < 8; nj++) {
            o[nj][0] *= a0; o[nj][1] *= a0;
            o[nj][2] *= a1; o[nj][3] *= a1;
        }

        // ---- O += P V (P fp16, V^T fp16 hi/lo 2-pass)
#pragma unroll
        for (int kt = 0; kt < 4; kt++) {
            uint32_t pkk[4];
            pkk[0] = pack_f16(sc[2*kt][0],   sc[2*kt][1]);
            pkk[1] = pack_f16(sc[2*kt][2],   sc[2*kt][3]);
            pkk[2] = pack_f16(sc[2*kt+1][0], sc[2*kt+1][1]);
            pkk[3] = pack_f16(sc[2*kt+1][2], sc[2*kt+1][3]);
            const uint32_t col = (uint32_t)((((kt << 1) | bchi) ^ bxr) << 4);
#pragma unroll
            for (int njj = 0; njj < 4; njj++) {
                const uint32_t rb = st + 8192 + (uint32_t)((njj << 4) + brl) * 128 + col;
                uint32_t vH[4], vL[4];
                ldmx4(vH, rb);
                ldmx4(vL, rb + 8192);
                mma16816f16(o[2*njj],   pkk, vH);
                mma16816f16(o[2*njj],   pkk, vL);
                mma16816f16(o[2*njj+1], pkk, vH + 2);
                mma16816f16(o[2*njj+1], pkk, vL + 2);
            }
        }
    }

    // ---- epilogue
    l0 += __shfl_xor_sync(0xffffffffu, l0, 1);
    l0 += __shfl_xor_sync(0xffffffffu, l0, 2);
    l1 += __shfl_xor_sync(0xffffffffu, l1, 1);
    l1 += __shfl_xor_sync(0xffffffffu, l1, 2);
    const float i0 = 1.0f / l0;
    const float i1 = 1.0f / l1;
    const size_t ro0 = ((size_t)(b * SS + q0 + (wid << 4) + (lane >> 2))) * DM + h * DK;
    const size_t ro1 = ro0 + (size_t)8 * DM;
#pragma unroll
    for (int nj = 0; nj < 8; nj++) {
        const int colg = (nj << 3) + cbase;
        uint32_t hi, lo;
        pack_hilo(o[nj][0] * i0, o[nj][1] * i0, hi, lo);
        *(uint32_t*)&g_attn_hi[ro0 + colg] = hi;
        *(uint32_t*)&g_attn_lo[ro0 + colg] = lo;
        pack_hilo(o[nj][2] * i1, o[nj][3] * i1, hi, lo);
        *(uint32_t*)&g_attn_hi[ro1 + colg] = hi;
        *(uint32_t*)&g_attn_lo[ro1 + colg] = lo;
    }
}

// ---------------------------------------------------------------------------
extern "C" void kernel_launch(void* const* d_in, const int* in_sizes, int n_in,
                              void* d_out, int out_size)
{
    const float* q    = (const float*)d_in[0];
    const float* k    = (const float*)d_in[1];
    const float* v    = (const float*)d_in[2];
    const int*   mask = (const int*)  d_in[3];
    const float* wq   = (const float*)d_in[4];
    const float* bq   = (const float*)d_in[5];
    const float* wk   = (const float*)d_in[6];
    const float* bk   = (const float*)d_in[7];
    const float* wv   = (const float*)d_in[8];
    const float* bv   = (const float*)d_in[9];
    const float* wo   = (const float*)d_in[10];
    const float* bo   = (const float*)d_in[11];
    float* out = (float*)d_out;

    cudaFuncSetAttribute(proj_kernel, cudaFuncAttributeMaxDynamicSharedMemorySize, TC_SMEM);
    cudaFuncSetAttribute(out_tc_kernel, cudaFuncAttributeMaxDynamicSharedMemorySize, TC_SMEM);
    cudaFuncSetAttribute(flash_mma_kernel, cudaFuncAttributeMaxDynamicSharedMemorySize, FLASH_SMEM);

    split_kernel<<<dim3(4096, 1, 7), 256>>>(q, k, v, wq, wk, wv, wo);
    mask_pack_kernel<<<256, 256>>>(mask);
    proj_kernel<<<768, 256, TC_SMEM>>>(bq, bk, bv);
    flash_mma_kernel<<<dim3(16, 16, 2), 256, FLASH_SMEM>>>(mask);
    out_tc_kernel<<<dim3(8, 32, 1), 256, TC_SMEM>>>(bo, out);
}

// round 17
// speedup vs baseline: 1.9649x; 1.2056x over previous
#include <cuda_runtime.h>
#include <cuda_fp16.h>
#include <cstdint>

#define BB 2
#define SS 2048
#define DM 1024
#define HH 16
#define DK 64

typedef unsigned long long ull;

#define ACT_N ((size_t)4096 * 1024)
#define W_N   ((size_t)1024 * 1024)

// Scratch (__device__ globals; allocation-free rule)
__device__ __align__(16) __half g_act16[2 * ACT_N];           // q,k inputs fp16
__device__ __align__(16) __half g_actv16_hi[ACT_N];           // v input fp16 hi/lo
__device__ __align__(16) __half g_actv16_lo[ACT_N];
__device__ __align__(16) __half g_w16[2 * W_N];               // wq,wk fp16
__device__ __align__(16) __half g_wv16[W_N];                  // wv fp16
__device__ __align__(16) __half g_wo16[W_N];                  // wo fp16
__device__ __align__(16) __half g_q16[BB*HH*SS*DK];           // [BH][S][64] (x0.125*log2e)
__device__ __align__(16) __half g_k16[BB*HH*SS*DK];           // [BH][S][64]
__device__ __align__(16) __half g_vt16[BB*HH*SS*DK];          // [BH][64][S] V^T fp16
__device__ __align__(16) __half g_attn_hi[ACT_N];             // flash out fp16 hi/lo
__device__ __align__(16) __half g_attn_lo[ACT_N];
__device__ ull g_maskbits[SS * (SS / 64)];                    // 512 KB bit mask

// ---------------- helpers ----------------
__device__ __forceinline__ uint32_t smem_u32(const void* p) {
    uint32_t a;
    asm("{ .reg .u64 t; cvta.to.shared.u64 t, %1; cvt.u32.u64 %0, t; }"
        : "=r"(a) : "l"(p));
    return a;
}
__device__ __forceinline__ uint64_t gmem_u64(const void* p) {
    uint64_t a;
    asm("cvta.to.global.u64 %0, %1;" : "=l"(a) : "l"(p));
    return a;
}
__device__ __forceinline__ void mma16816f16(float* c, const uint32_t* a, const uint32_t* b) {
    asm volatile(
        "mma.sync.aligned.m16n8k16.row.col.f32.f16.f16.f32 "
        "{%0,%1,%2,%3}, {%4,%5,%6,%7}, {%8,%9}, {%0,%1,%2,%3};"
        : "+f"(c[0]), "+f"(c[1]), "+f"(c[2]), "+f"(c[3])
        : "r"(a[0]), "r"(a[1]), "r"(a[2]), "r"(a[3]), "r"(b[0]), "r"(b[1]));
}
__device__ __forceinline__ void ldmx4(uint32_t* r, uint32_t addr) {
    asm volatile("ldmatrix.sync.aligned.m8n8.x4.shared.b16 {%0,%1,%2,%3}, [%4];"
                 : "=r"(r[0]), "=r"(r[1]), "=r"(r[2]), "=r"(r[3]) : "r"(addr));
}
__device__ __forceinline__ void cp16(uint32_t saddr, uint64_t gaddr) {
    asm volatile("cp.async.cg.shared.global [%0], [%1], 16;"
                 :: "r"(saddr), "l"(gaddr) : "memory");
}
#define CP_COMMIT() asm volatile("cp.async.commit_group;" ::: "memory")
#define CP_WAIT(n)  asm volatile("cp.async.wait_group %0;" :: "n"(n) : "memory")

__device__ __forceinline__ uint32_t swz(uint32_t x) { return x ^ ((x >> 3) & 0x70); }

__device__ __forceinline__ float ex2f(float x) {
    float y; asm("ex2.approx.f32 %0, %1;" : "=f"(y) : "f"(x)); return y;
}

// pack two fp32 -> f16x2 hi + f16x2 residual lo
__device__ __forceinline__ void pack_hilo_f16(float x0, float x1, uint32_t& hi, uint32_t& lo) {
    uint32_t h;
    asm("cvt.rn.f16x2.f32 %0, %1, %2;" : "=r"(h) : "f"(x1), "f"(x0));
    float h0, h1;
    asm("{ .reg .f16 a,b;\n\t mov.b32 {a,b}, %2;\n\t cvt.f32.f16 %0, a;\n\t cvt.f32.f16 %1, b; }"
        : "=f"(h0), "=f"(h1) : "r"(h));
    uint32_t l;
    asm("cvt.rn.f16x2.f32 %0, %1, %2;" : "=r"(l) : "f"(x1 - h1), "f"(x0 - h0));
    hi = h; lo = l;
}
// pack two fp32 -> single f16x2
__device__ __forceinline__ uint32_t pack_f16(float x0, float x1) {
    uint32_t r;
    asm("cvt.rn.f16x2.f32 %0, %1, %2;" : "=r"(r) : "f"(x1), "f"(x0));
    return r;
}

// ---------------------------------------------------------------------------
// Mask -> bit pack
// ---------------------------------------------------------------------------
__global__ void __launch_bounds__(256)
mask_pack_kernel(const int* __restrict__ mask)
{
    const int w = blockIdx.x * 256 + threadIdx.x;
    const int r = w >> 5, cw = w & 31;
    const int4* src = (const int4*)(mask + (size_t)r * SS + (cw << 6));
    ull bits = 0;
#pragma unroll
    for (int i = 0; i < 16; i++) {
        const int4 v = src[i];
        bits |= (ull)(v.x != 0) << (i * 4);
        bits |= (ull)(v.y != 0) << (i * 4 + 1);
        bits |= (ull)(v.z != 0) << (i * 4 + 2);
        bits |= (ull)(v.w != 0) << (i * 4 + 3);
    }
    g_maskbits[w] = bits;
}

// ---------------------------------------------------------------------------
// Split kernel. z=0:q z=1:k z=3:wq z=4:wk z=5:wv z=6:wo -> fp16 single.
// z=2: v -> fp16 hi/lo.
// ---------------------------------------------------------------------------
__global__ void __launch_bounds__(256)
split_kernel(const float* __restrict__ q, const float* __restrict__ k,
             const float* __restrict__ v,
             const float* __restrict__ wq, const float* __restrict__ wk,
             const float* __restrict__ wv, const float* __restrict__ wo)
{
    const int z = blockIdx.z;
    const size_t i4 = (size_t)blockIdx.x * 256 + threadIdx.x;

    if (z == 2) {
        if (i4 * 4 >= ACT_N) return;
        float4 x = ((const float4*)v)[i4];
        uint32_t h01, l01, h23, l23;
        pack_hilo_f16(x.x, x.y, h01, l01);
        pack_hilo_f16(x.z, x.w, h23, l23);
        *(uint2*)&g_actv16_hi[i4 * 4] = make_uint2(h01, h23);
        *(uint2*)&g_actv16_lo[i4 * 4] = make_uint2(l01, l23);
    } else {
        const float* src;
        __half* d16;
        size_t cnt;
        if (z == 0)      { src = q;  d16 = g_act16;          cnt = ACT_N; }
        else if (z == 1) { src = k;  d16 = g_act16 + ACT_N;  cnt = ACT_N; }
        else if (z == 3) { src = wq; d16 = g_w16;            cnt = W_N; }
        else if (z == 4) { src = wk; d16 = g_w16 + W_N;      cnt = W_N; }
        else if (z == 5) { src = wv; d16 = g_wv16;           cnt = W_N; }
        else             { src = wo; d16 = g_wo16;           cnt = W_N; }
        if (i4 * 4 >= cnt) return;
        float4 x = ((const float4*)src)[i4];
        *(uint2*)&d16[i4 * 4] = make_uint2(pack_f16(x.x, x.y), pack_f16(x.z, x.w));
    }
}

// ---------------------------------------------------------------------------
// 2-pass fp16 GEMM. 128x128 tile, K=1024, 3-stage pipeline (48KB/stage).
// MODE 0 (out proj): P0=Ah, P1=Al (attn hi/lo), P2=B (wo single);
//                    C[m][n] fp32 = (Ah+Al)@B^T + bias[n].
// MODE 1 (V^T proj): P0=A (wv single), P1=Bh, P2=Bl (x hi/lo);
//                    D fp16 transposed [BH][64][S] = A@(Bh+Bl)^T + bias[m].
// ---------------------------------------------------------------------------
#define STAGE2P 49152
#define TC2_SMEM (3 * STAGE2P)   // 144 KB

template <int MODE>
__device__ __forceinline__ void gemm_2p(int m0, int n0,
                                        const __half* __restrict__ P0,
                                        const __half* __restrict__ P1,
                                        const __half* __restrict__ P2,
                                        const float* __restrict__ bias,
                                        float* __restrict__ C,
                                        __half* __restrict__ D)
{
    extern __shared__ char sm[];
    const uint32_t smb = smem_u32(sm);
    const int tid  = threadIdx.x;
    const int wid  = tid >> 5;
    const int lane = tid & 31;

    const int warp_m = (wid >> 2) << 6;
    const int warp_n = (wid & 3) << 5;

    uint64_t g0 = gmem_u64(P0 + (size_t)m0 * 1024);
    uint64_t g1, g2;
    if (MODE == 0) {
        g1 = gmem_u64(P1 + (size_t)m0 * 1024);
        g2 = gmem_u64(P2 + (size_t)n0 * 1024);
    } else {
        g1 = gmem_u64(P1 + (size_t)n0 * 1024);
        g2 = gmem_u64(P2 + (size_t)n0 * 1024);
    }

    const int lr = tid >> 3;
    const int lc = tid & 7;

    const int arow = warp_m + (lane & 15);
    const int a_chi = lane >> 4;
    const int ax = arow & 7;
    const uint32_t arow128 = (uint32_t)arow * 128;
    const int g = lane >> 3;
    const int brow = warp_n + ((g >> 1) << 3) + (lane & 7);
    const int b_chi = g & 1;
    const int bx = brow & 7;
    const uint32_t brow128 = (uint32_t)brow * 128;

    float acc[4][4][4];
#pragma unroll
    for (int mi = 0; mi < 4; mi++)
#pragma unroll
        for (int nj = 0; nj < 4; nj++)
#pragma unroll
            for (int r = 0; r < 4; r++) acc[mi][nj][r] = 0.f;

    auto issue_chunk = [&](int c) {
        const int k0 = c << 6;
        const uint32_t st = smb + (uint32_t)(c % 3) * STAGE2P;
#pragma unroll
        for (int rb = 0; rb < 4; rb++) {
            const int row = (rb << 5) + lr;
            const uint32_t so = swz((uint32_t)row * 128 + (lc << 4));
            const uint64_t off = ((size_t)row * 1024 + k0 + (lc << 3)) * 2;
            cp16(st + so,         g0 + off);
            cp16(st + 16384 + so, g1 + off);
            cp16(st + 32768 + so, g2 + off);
        }
        CP_COMMIT();
    };

    issue_chunk(0);
    issue_chunk(1);

    for (int c = 0; c < 16; c++) {
        if (c < 15) { CP_WAIT(1); } else { CP_WAIT(0); }
        __syncthreads();
        if (c + 2 < 16) issue_chunk(c + 2);

        const uint32_t st = smb + (uint32_t)(c % 3) * STAGE2P;

#pragma unroll
        for (int ks = 0; ks < 4; ks++) {
            const uint32_t acol = (uint32_t)((((ks << 1) | a_chi) ^ ax) << 4);
            const uint32_t bcol = (uint32_t)((((ks << 1) | b_chi) ^ bx) << 4);

            if (MODE == 0) {
                uint32_t Ahf[4][4], Alf[4][4], Bf[4][2];
#pragma unroll
                for (int mi = 0; mi < 4; mi++) {
                    const uint32_t ad = st + arow128 + mi * 2048 + acol;
                    ldmx4(Ahf[mi], ad);
                    ldmx4(Alf[mi], ad + 16384);
                }
#pragma unroll
                for (int njj = 0; njj < 2; njj++) {
                    uint32_t t[4];
                    ldmx4(t, st + 32768 + brow128 + njj * 2048 + bcol);
                    Bf[njj*2][0] = t[0]; Bf[njj*2][1] = t[1];
                    Bf[njj*2+1][0] = t[2]; Bf[njj*2+1][1] = t[3];
                }
#pragma unroll
                for (int mi = 0; mi < 4; mi++)
#pragma unroll
                    for (int nj = 0; nj < 4; nj++) {
                        mma16816f16(acc[mi][nj], Ahf[mi], Bf[nj]);
                        mma16816f16(acc[mi][nj], Alf[mi], Bf[nj]);
                    }
            } else {
                uint32_t Af[4][4], Bhf[4][2], Blf[4][2];
#pragma unroll
                for (int mi = 0; mi < 4; mi++)
                    ldmx4(Af[mi], st + arow128 + mi * 2048 + acol);
#pragma unroll
                for (int njj = 0; njj < 2; njj++) {
                    const uint32_t bd = st + 16384 + brow128 + njj * 2048 + bcol;
                    uint32_t t[4];
                    ldmx4(t, bd);
                    Bhf[njj*2][0] = t[0]; Bhf[njj*2][1] = t[1];
                    Bhf[njj*2+1][0] = t[2]; Bhf[njj*2+1][1] = t[3];
                    ldmx4(t, bd + 16384);
                    Blf[njj*2][0] = t[0]; Blf[njj*2][1] = t[1];
                    Blf[njj*2+1][0] = t[2]; Blf[njj*2+1][1] = t[3];
                }
#pragma unroll
                for (int mi = 0; mi < 4; mi++)
#pragma unroll
                    for (int nj = 0; nj < 4; nj++) {
                        mma16816f16(acc[mi][nj], Af[mi], Bhf[nj]);
                        mma16816f16(acc[mi][nj], Af[mi], Blf[nj]);
                    }
            }
        }
    }
    __syncthreads();

    float* eps = (float*)sm;
    const int eg = lane >> 2;
    const int eco = (lane & 3) << 1;
#pragma unroll
    for (int mi = 0; mi < 4; mi++)
#pragma unroll
        for (int nj = 0; nj < 4; nj++) {
            const int row0 = warp_m + (mi << 4) + eg;
            const int col  = warp_n + (nj << 3) + eco;
            *(float2*)&eps[row0 * 136 + col] = make_float2(acc[mi][nj][0], acc[mi][nj][1]);
            *(float2*)&eps[(row0 + 8) * 136 + col] = make_float2(acc[mi][nj][2], acc[mi][nj][3]);
        }
    __syncthreads();

#pragma unroll
    for (int i = 0; i < 16; i++) {
        const int idx = tid + (i << 8);
        const int row = idx >> 5;
        const int c4  = idx & 31;
        const int n   = n0 + (c4 << 2);
        const int m   = m0 + row;
        float4 v = *(const float4*)&eps[row * 136 + (c4 << 2)];
        if (MODE == 0) {
            const float4 bb = *(const float4*)&bias[n];
            v.x += bb.x; v.y += bb.y; v.z += bb.z; v.w += bb.w;
            *(float4*)&C[(size_t)m * 1024 + n] = v;
        } else {
            const float bb = bias[m];
            v.x += bb; v.y += bb; v.z += bb; v.w += bb;
            const int h0 = m >> 6, d = m & 63, bq_ = n >> 11, s = n & 2047;
            const size_t base = (((size_t)(bq_ * HH + h0)) * DK + d) * SS + s;
            *(uint2*)&D[base] = make_uint2(pack_f16(v.x, v.y), pack_f16(v.z, v.w));
        }
    }
}

// ---------------------------------------------------------------------------
// Single-pass fp16 GEMM for Q/K projections (unchanged from r16).
// ---------------------------------------------------------------------------
#define STAGE16 32768

__device__ __forceinline__ void gemm16(int m0, int n0,
                                       const __half* __restrict__ A,
                                       const __half* __restrict__ B,
                                       const float* __restrict__ bias,
                                       __half* __restrict__ Dq, float oscale)
{
    extern __shared__ char sm[];
    const uint32_t smb = smem_u32(sm);
    const int tid  = threadIdx.x;
    const int wid  = tid >> 5;
    const int lane = tid & 31;

    const int warp_m = (wid >> 2) << 6;
    const int warp_n = (wid & 3) << 5;

    const uint64_t gA = gmem_u64(A + (size_t)m0 * 1024);
    const uint64_t gB = gmem_u64(B + (size_t)n0 * 1024);

    const int lr = tid >> 3;
    const int lc = tid & 7;

    const int arow = warp_m + (lane & 15);
    const int a_chi = lane >> 4;
    const int ax = arow & 7;
    const uint32_t arow128 = (uint32_t)arow * 128;
    const int g = lane >> 3;
    const int brow = warp_n + ((g >> 1) << 3) + (lane & 7);
    const int b_chi = g & 1;
    const int bx = brow & 7;
    const uint32_t brow128 = (uint32_t)brow * 128;

    float acc[4][4][4];
#pragma unroll
    for (int mi = 0; mi < 4; mi++)
#pragma unroll
        for (int nj = 0; nj < 4; nj++)
#pragma unroll
            for (int r = 0; r < 4; r++) acc[mi][nj][r] = 0.f;

    auto issue_chunk = [&](int c) {
        const int k0 = c << 6;
        const uint32_t st = smb + (uint32_t)(c % 3) * STAGE16;
#pragma unroll
        for (int rb = 0; rb < 4; rb++) {
            const int row = (rb << 5) + lr;
            const uint32_t so = swz((uint32_t)row * 128 + (lc << 4));
            const uint64_t off = ((size_t)row * 1024 + k0 + (lc << 3)) * 2;
            cp16(st + so,         gA + off);
            cp16(st + 16384 + so, gB + off);
        }
        CP_COMMIT();
    };

    issue_chunk(0);
    issue_chunk(1);

    for (int c = 0; c < 16; c++) {
        if (c < 15) { CP_WAIT(1); } else { CP_WAIT(0); }
        __syncthreads();
        if (c + 2 < 16) issue_chunk(c + 2);

        const uint32_t st = smb + (uint32_t)(c % 3) * STAGE16;

#pragma unroll
        for (int ks = 0; ks < 4; ks++) {
            uint32_t Af[4][4], Bf[4][2];
            const uint32_t acol = (uint32_t)((((ks << 1) | a_chi) ^ ax) << 4);
            const uint32_t bcol = (uint32_t)((((ks << 1) | b_chi) ^ bx) << 4);
#pragma unroll
            for (int mi = 0; mi < 4; mi++)
                ldmx4(Af[mi], st + arow128 + mi * 2048 + acol);
#pragma unroll
            for (int njj = 0; njj < 2; njj++) {
                uint32_t t[4];
                ldmx4(t, st + 16384 + brow128 + njj * 2048 + bcol);
                Bf[njj*2][0] = t[0]; Bf[njj*2][1] = t[1];
                Bf[njj*2+1][0] = t[2]; Bf[njj*2+1][1] = t[3];
            }
#pragma unroll
            for (int mi = 0; mi < 4; mi++)
#pragma unroll
                for (int nj = 0; nj < 4; nj++)
                    mma16816f16(acc[mi][nj], Af[mi], Bf[nj]);
        }
    }
    __syncthreads();

    float* eps = (float*)sm;
    const int eg = lane >> 2;
    const int eco = (lane & 3) << 1;
#pragma unroll
    for (int mi = 0; mi < 4; mi++)
#pragma unroll
        for (int nj = 0; nj < 4; nj++) {
            const int row0 = warp_m + (mi << 4) + eg;
            const int col  = warp_n + (nj << 3) + eco;
            *(float2*)&eps[row0 * 136 + col] = make_float2(acc[mi][nj][0], acc[mi][nj][1]);
            *(float2*)&eps[(row0 + 8) * 136 + col] = make_float2(acc[mi][nj][2], acc[mi][nj][3]);
        }
    __syncthreads();

#pragma unroll
    for (int i = 0; i < 16; i++) {
        const int idx = tid + (i << 8);
        const int row = idx >> 5;
        const int c4  = idx & 31;
        const int n   = n0 + (c4 << 2);
        const int m   = m0 + row;
        float4 v = *(const float4*)&eps[row * 136 + (c4 << 2)];
        const float4 bb = *(const float4*)&bias[n];
        v.x = (v.x + bb.x) * oscale; v.y = (v.y + bb.y) * oscale;
        v.z = (v.z + bb.z) * oscale; v.w = (v.w + bb.w) * oscale;
        const int bq_ = m >> 11, s = m & 2047, h0 = n >> 6, d = n & 63;
        const size_t base = (((size_t)(bq_ * HH + h0)) * SS + s) * DK + d;
        *(uint2*)&Dq[base] = make_uint2(pack_f16(v.x, v.y), pack_f16(v.z, v.w));
    }
}

// Merged Q/K/V projection: [0,256)=Q fp16, [256,512)=K fp16, [512,768)=V^T 2p.
__global__ void __launch_bounds__(256, 1)
proj_kernel(const float* __restrict__ bq, const float* __restrict__ bk,
            const float* __restrict__ bv)
{
    const int bid = blockIdx.x;
    if (bid < 512) {
        const int z = bid >> 8;
        const int t = bid & 255;
        const int m0 = (t >> 3) << 7;
        const int n0 = (t & 7) << 7;
        if (z == 0)
            gemm16(m0, n0, g_act16, g_w16, bq, g_q16,
                   0.125f * 1.4426950408889634f);
        else
            gemm16(m0, n0, g_act16 + ACT_N, g_w16 + W_N, bk, g_k16, 1.0f);
    } else {
        const int t = bid - 512;
        const int m0 = (t >> 5) << 7;
        const int n0 = (t & 31) << 7;
        gemm_2p<1>(m0, n0, g_wv16, g_actv16_hi, g_actv16_lo, bv, nullptr, g_vt16);
    }
}

__global__ void __launch_bounds__(256, 1)
out_tc_kernel(const float* __restrict__ bo, float* __restrict__ out)
{
    const int m0 = blockIdx.y << 7;
    const int n0 = blockIdx.x << 7;
    gemm_2p<0>(m0, n0, g_attn_hi, g_attn_lo, g_wo16, bo, out, nullptr);
}

// ---------------------------------------------------------------------------
// Flash attention: fp16 single QK + single-pass fp16 PV. 2 CTAs/SM.
// smem: [0,16K) Q fp16, [16K,64K) 3-stage ring (K|V, 8KB each = 16KB/stage).
// Single sync/tile, bitmask, log2 softmax, lane-partial l.
// ---------------------------------------------------------------------------
#define FLASH_STAGE 16384
#define FLASH_SMEM (16384 + 3 * FLASH_STAGE)   // 64 KB

__global__ void __launch_bounds__(256, 2)
flash_mma_kernel(const int* __restrict__ mask)
{
    extern __shared__ char sm[];
    const uint32_t smb = smem_u32(sm);
    const uint32_t ring = smb + 16384;
    const int tid  = threadIdx.x;
    const int wid  = tid >> 5;
    const int lane = tid & 31;
    const int b = blockIdx.z, h = blockIdx.y;
    const int bh = b * HH + h;
    const int q0 = blockIdx.x << 7;

    const int lr = tid >> 3;
    const int lc = tid & 7;

    // ---- stage Q (fp16) into [0,16K)
    {
        const uint64_t gq = gmem_u64(g_q16 + ((size_t)bh * SS + q0) * DK);
#pragma unroll
        for (int rs = 0; rs < 4; rs++) {
            const int row = (rs << 5) + lr;
            cp16(smb + swz((uint32_t)row * 128 + (lc << 4)),
                 gq + ((size_t)row * 64 + (lc << 3)) * 2);
        }
        CP_COMMIT(); CP_WAIT(0);
        __syncthreads();
    }

    const int arowA = (wid << 4) + (lane & 15);
    const int a_chi = lane >> 4;
    const int axA = arowA & 7;
    const uint32_t arowA128 = (uint32_t)arowA * 128;

    uint32_t qh[4][4];
#pragma unroll
    for (int ks = 0; ks < 4; ks++) {
        const uint32_t col = (uint32_t)((((ks << 1) | a_chi) ^ axA) << 4);
        ldmx4(qh[ks], smb + arowA128 + col);
    }

    const uint64_t gk = gmem_u64(g_k16 + (size_t)bh * SS * DK);
    const uint64_t gv = gmem_u64(g_vt16 + (size_t)bh * DK * SS);

    auto issue = [&](int t) {
        const uint32_t st = ring + (uint32_t)(t % 3) * FLASH_STAGE;
        const int kv0 = t << 6;
#pragma unroll
        for (int rs = 0; rs < 2; rs++) {
            const int row = (rs << 5) + lr;
            const uint32_t so = swz((uint32_t)row * 128 + (lc << 4));
            cp16(st + so,        gk + (((size_t)(kv0 + row)) * 64 + (lc << 3)) * 2);
            cp16(st + 8192 + so, gv + ((size_t)row * SS + kv0 + (lc << 3)) * 2);
        }
        CP_COMMIT();
    };

    issue(0);
    issue(1);

    const int gq_ = lane >> 3;
    const int brl = ((gq_ >> 1) << 3) | (lane & 7);
    const int bchi = gq_ & 1;
    const int bxr = brl & 7;

    const int qrow = q0 + (wid << 4) + (lane >> 2);
    const ull* mb0 = g_maskbits + (size_t)qrow * 32;
    const ull* mb1 = mb0 + 8 * 32;
    const int cbase = (lane & 3) << 1;

    float o[8][4];
#pragma unroll
    for (int nj = 0; nj < 8; nj++)
#pragma unroll
        for (int r = 0; r < 4; r++) o[nj][r] = 0.f;
    float m0 = -3e38f, m1 = -3e38f, l0 = 0.f, l1 = 0.f;

    for (int t = 0; t < 32; t++) {
        if (t < 31) { CP_WAIT(1); } else { CP_WAIT(0); }
        __syncthreads();
        if (t + 2 < 32) issue(t + 2);

        const uint32_t st = ring + (uint32_t)(t % 3) * FLASH_STAGE;

        const ull w0 = mb0[t];
        const ull w1 = mb1[t];

        // ---- S = Q K^T (single-pass fp16)
        float sc[8][4];
#pragma unroll
        for (int nj = 0; nj < 8; nj++)
#pragma unroll
            for (int r = 0; r < 4; r++) sc[nj][r] = 0.f;

#pragma unroll
        for (int ks = 0; ks < 4; ks++) {
            const uint32_t col = (uint32_t)((((ks << 1) | bchi) ^ bxr) << 4);
#pragma unroll
            for (int njj = 0; njj < 4; njj++) {
                uint32_t tK[4];
                ldmx4(tK, st + (uint32_t)((njj << 4) + brl) * 128 + col);
                mma16816f16(sc[2*njj],   qh[ks], tK);
                mma16816f16(sc[2*njj+1], qh[ks], tK + 2);
            }
        }

        // ---- mask + online softmax (log2 domain)
        float mx0 = -3e38f, mx1 = -3e38f;
#pragma unroll
        for (int nj = 0; nj < 8; nj++) {
            const int sh = (nj << 3) + cbase;
            const uint32_t b0 = (uint32_t)(w0 >> sh);
            const uint32_t b1 = (uint32_t)(w1 >> sh);
            sc[nj][0] = (b0 & 1) ? sc[nj][0] : -1e9f;
            sc[nj][1] = (b0 & 2) ? sc[nj][1] : -1e9f;
            sc[nj][2] = (b1 & 1) ? sc[nj][2] : -1e9f;
            sc[nj][3] = (b1 & 2) ? sc[nj][3] : -1e9f;
            mx0 = fmaxf(mx0, fmaxf(sc[nj][0], sc[nj][1]));
            mx1 = fmaxf(mx1, fmaxf(sc[nj][2], sc[nj][3]));
        }
        mx0 = fmaxf(mx0, __shfl_xor_sync(0xffffffffu, mx0, 1));
        mx0 = fmaxf(mx0, __shfl_xor_sync(0xffffffffu, mx0, 2));
        mx1 = fmaxf(mx1, __shfl_xor_sync(0xffffffffu, mx1, 1));
        mx1 = fmaxf(mx1, __shfl_xor_sync(0xffffffffu, mx1, 2));

        const float mn0 = fmaxf(m0, mx0);
        const float mn1 = fmaxf(m1, mx1);
        const float a0 = ex2f(m0 - mn0);
        const float a1 = ex2f(m1 - mn1);
        m0 = mn0; m1 = mn1;

        float s0 = 0.f, s1 = 0.f;
#pragma unroll
        for (int nj = 0; nj < 8; nj++) {
            sc[nj][0] = ex2f(sc[nj][0] - mn0);
            sc[nj][1] = ex2f(sc[nj][1] - mn0);
            sc[nj][2] = ex2f(sc[nj][2] - mn1);
            sc[nj][3] = ex2f(sc[nj][3] - mn1);
            s0 += sc[nj][0] + sc[nj][1];
            s1 += sc[nj][2] + sc[nj][3];
        }
        l0 = l0 * a0 + s0;
        l1 = l1 * a1 + s1;

#pragma unroll
        for (int nj = 0; nj < 8; nj++) {
            o[nj][0] *= a0; o[nj][1] *= a0;
            o[nj][2] *= a1; o[nj][3] *= a1;
        }

        // ---- O += P V (P fp16, V^T fp16 single-pass)
#pragma unroll
        for (int kt = 0; kt < 4; kt++) {
            uint32_t pkk[4];
            pkk[0] = pack_f16(sc[2*kt][0],   sc[2*kt][1]);
            pkk[1] = pack_f16(sc[2*kt][2],   sc[2*kt][3]);
            pkk[2] = pack_f16(sc[2*kt+1][0], sc[2*kt+1][1]);
            pkk[3] = pack_f16(sc[2*kt+1][2], sc[2*kt+1][3]);
            const uint32_t col = (uint32_t)((((kt << 1) | bchi) ^ bxr) << 4);
#pragma unroll
            for (int njj = 0; njj < 4; njj++) {
                uint32_t vH[4];
                ldmx4(vH, st + 8192 + (uint32_t)((njj << 4) + brl) * 128 + col);
                mma16816f16(o[2*njj],   pkk, vH);
                mma16816f16(o[2*njj+1], pkk, vH + 2);
            }
        }
    }

    // ---- epilogue: quad-reduce l, normalize, write fp16 hi/lo attn
    l0 += __shfl_xor_sync(0xffffffffu, l0, 1);
    l0 += __shfl_xor_sync(0xffffffffu, l0, 2);
    l1 += __shfl_xor_sync(0xffffffffu, l1, 1);
    l1 += __shfl_xor_sync(0xffffffffu, l1, 2);
    const float i0 = 1.0f / l0;
    const float i1 = 1.0f / l1;
    const size_t ro0 = ((size_t)(b * SS + q0 + (wid << 4) + (lane >> 2))) * DM + h * DK;
    const size_t ro1 = ro0 + (size_t)8 * DM;
#pragma unroll
    for (int nj = 0; nj < 8; nj++) {
        const int colg = (nj << 3) + cbase;
        uint32_t hi, lo;
        pack_hilo_f16(o[nj][0] * i0, o[nj][1] * i0, hi, lo);
        *(uint32_t*)&g_attn_hi[ro0 + colg] = hi;
        *(uint32_t*)&g_attn_lo[ro0 + colg] = lo;
        pack_hilo_f16(o[nj][2] * i1, o[nj][3] * i1, hi, lo);
        *(uint32_t*)&g_attn_hi[ro1 + colg] = hi;
        *(uint32_t*)&g_attn_lo[ro1 + colg] = lo;
    }
}

// ---------------------------------------------------------------------------
extern "C" void kernel_launch(void* const* d_in, const int* in_sizes, int n_in,
                              void* d_out, int out_size)
{
    const float* q    = (const float*)d_in[0];
    const float* k    = (const float*)d_in[1];
    const float* v    = (const float*)d_in[2];
    const int*   mask = (const int*)  d_in[3];
    const float* wq   = (const float*)d_in[4];
    const float* bq   = (const float*)d_in[5];
    const float* wk   = (const float*)d_in[6];
    const float* bk   = (const float*)d_in[7];
    const float* wv   = (const float*)d_in[8];
    const float* bv   = (const float*)d_in[9];
    const float* wo   = (const float*)d_in[10];
    const float* bo   = (const float*)d_in[11];
    float* out = (float*)d_out;

    cudaFuncSetAttribute(proj_kernel, cudaFuncAttributeMaxDynamicSharedMemorySize, TC2_SMEM);
    cudaFuncSetAttribute(out_tc_kernel, cudaFuncAttributeMaxDynamicSharedMemorySize, TC2_SMEM);
    cudaFuncSetAttribute(flash_mma_kernel, cudaFuncAttributeMaxDynamicSharedMemorySize, FLASH_SMEM);

    split_kernel<<<dim3(4096, 1, 7), 256>>>(q, k, v, wq, wk, wv, wo);
    mask_pack_kernel<<<256, 256>>>(mask);
    proj_kernel<<<768, 256, TC2_SMEM>>>(bq, bk, bv);
    flash_mma_kernel<<<dim3(16, 16, 2), 256, FLASH_SMEM>>>(mask);
    out_tc_kernel<<<dim3(8, 32, 1), 256, TC2_SMEM>>>(bo, out);
}